// round 5
// baseline (speedup 1.0000x reference)
#include <cuda_runtime.h>
#include <cuda_bf16.h>
#include <math.h>
#include <stdint.h>

// Problem constants
#define Bb   16
#define Ss   4096
#define Hh   12
#define Dd   64
constexpr int M = Bb * Ss;   // 65536
constexpr int NQKV = 2304;   // merged Q|K|V columns

// ---------------------------------------------------------------------------
// Scratch (device globals)
// ---------------------------------------------------------------------------
__device__ float g_qkv[(size_t)M * NQKV];          // Q | K | V fp32
__device__ int8_t g_x8a[(size_t)M * 768];          // x quant level 1
__device__ int8_t g_x8b[(size_t)M * 768];          // x quant level 2
__device__ float  g_s1x[M];                        // per-row scale of x
__device__ int8_t g_w8a[(size_t)NQKV * 768];       // Wqkv^T quant level 1
__device__ int8_t g_w8b[(size_t)NQKV * 768];       // level 2
__device__ float  g_t1w[NQKV];                     // per-col scale of W
__device__ float  g_biasc[NQKV];                   // concat bias
__device__ __nv_bfloat16 g_ahi[(size_t)M * 768];   // attn out hi
__device__ __nv_bfloat16 g_alo[(size_t)M * 768];   // attn out lo
__device__ __nv_bfloat16 g_whi[768 * 768];         // Wo^T hi
__device__ __nv_bfloat16 g_wlo[768 * 768];         // Wo^T lo
__device__ float g_kv[Bb * Hh * Dd * Dd];
__device__ float g_ksum[Bb * Hh * Dd];
__device__ float g_kvp[4][Bb * Hh][Dd * Dd];
__device__ float g_ksp[4][Bb * Hh][Dd];

// ---------------------------------------------------------------------------
// PTX helpers (sm_80-compatible: cp.async, ldmatrix, mma.sync)
// ---------------------------------------------------------------------------
__device__ __forceinline__ uint32_t smem_u32(const void* p) {
    uint32_t a;
    asm("{ .reg .u64 t; cvta.to.shared.u64 t, %1; cvt.u32.u64 %0, t; }"
        : "=r"(a) : "l"(p));
    return a;
}

__device__ __forceinline__ void cpa16(uint32_t dst, const void* src) {
    asm volatile("cp.async.cg.shared.global [%0], [%1], 16;" :: "r"(dst), "l"(src) : "memory");
}
#define CP_COMMIT() asm volatile("cp.async.commit_group;" ::: "memory")
#define CP_WAIT(n)  asm volatile("cp.async.wait_group %0;" :: "n"(n) : "memory")

__device__ __forceinline__ void ldsm4(uint32_t* r, uint32_t addr) {
    asm volatile("ldmatrix.sync.aligned.m8n8.x4.shared.b16 {%0,%1,%2,%3}, [%4];"
                 : "=r"(r[0]), "=r"(r[1]), "=r"(r[2]), "=r"(r[3]) : "r"(addr));
}

__device__ __forceinline__ void mma_bf16(float* c, const uint32_t* a, const uint32_t* b) {
    asm volatile(
        "mma.sync.aligned.m16n8k16.row.col.f32.bf16.bf16.f32 "
        "{%0,%1,%2,%3}, {%4,%5,%6,%7}, {%8,%9}, {%0,%1,%2,%3};"
        : "+f"(c[0]), "+f"(c[1]), "+f"(c[2]), "+f"(c[3])
        : "r"(a[0]), "r"(a[1]), "r"(a[2]), "r"(a[3]), "r"(b[0]), "r"(b[1]));
}

__device__ __forceinline__ void mma_s8(int* c, const uint32_t* a, const uint32_t* b) {
    asm volatile(
        "mma.sync.aligned.m16n8k32.row.col.s32.s8.s8.s32 "
        "{%0,%1,%2,%3}, {%4,%5,%6,%7}, {%8,%9}, {%0,%1,%2,%3};"
        : "+r"(c[0]), "+r"(c[1]), "+r"(c[2]), "+r"(c[3])
        : "r"(a[0]), "r"(a[1]), "r"(a[2]), "r"(a[3]), "r"(b[0]), "r"(b[1]));
}

__device__ __forceinline__ float epi_f(float v, float mk, int epi) {
    if (epi >= 1) v *= mk;
    if (epi == 2) { v = (v > 0.0f) ? (v + 1.0f) : expf(v); v *= 0.125f; }
    return v;
}

// ---------------------------------------------------------------------------
// Int8 2-level GEMM (QKV merged):
//   C[M, 2304] = x[M,768] @ Wqkv^T, then per-column-block epilogue.
//   x ~ s1[m]*(a1 + a2/252), W ~ t1[n]*(b1 + b2/252)
//   kept terms: a1b1 (P11), a1b2 + a2b1 (Pc, shared scale s1t1/252)
// CTA tile 128x128x64, 8 warps (64x32 warp tile), 3-stage cp.async.
// Smem/stage: A1 8K | A2 8K | B1 8K | B2 8K = 32KB.
// ---------------------------------------------------------------------------
constexpr int I8_STAGE = 32768;
constexpr int I8_SMEM  = 3 * I8_STAGE;
constexpr int XA1 = 0, XA2 = 8192, XB1 = 16384, XB2 = 24576;

__device__ __forceinline__ void stage_load_i8(
    uint32_t sbase,
    const int8_t* __restrict__ A1, const int8_t* __restrict__ A2,
    const int8_t* __restrict__ B1, const int8_t* __restrict__ B2,
    int mb, int nb, int k0, int tid)
{
    #pragma unroll
    for (int t = 0; t < 2; t++) {
        const int lin = tid + t * 256;    // 512 slots: 128 rows x 4 chunks
        const int r = lin >> 2;
        const int c = lin & 3;
        const uint32_t so = (uint32_t)r * 64 + ((uint32_t)(c ^ ((r >> 1) & 3)) << 4);
        const size_t ga = (size_t)(mb + r) * 768 + k0 + c * 16;
        const size_t gb = (size_t)(nb + r) * 768 + k0 + c * 16;
        cpa16(sbase + XA1 + so, A1 + ga);
        cpa16(sbase + XA2 + so, A2 + ga);
        cpa16(sbase + XB1 + so, B1 + gb);
        cpa16(sbase + XB2 + so, B2 + gb);
    }
}

__global__ void __launch_bounds__(256, 1)
gemm_i8(const int8_t* __restrict__ A1, const int8_t* __restrict__ A2,
        const int8_t* __restrict__ B1, const int8_t* __restrict__ B2,
        const float* __restrict__ s1x, const float* __restrict__ t1w,
        const float* __restrict__ bias, const float* __restrict__ mask,
        float* __restrict__ C)
{
    extern __shared__ char smraw[];
    const uint32_t sm0 = smem_u32(smraw);

    const int tid  = threadIdx.x;
    const int lane = tid & 31;
    const int warp = tid >> 5;
    const int wm = warp & 1;        // 2 warps in M -> 64 rows
    const int wn = warp >> 1;       // 4 warps in N -> 32 cols
    const int nb = blockIdx.x * 128;
    const int mb = blockIdx.y * 128;
    const int epi = (blockIdx.x < 12) ? 2 : 1;   // Q,K blocks 0-11; V 12-17

    // A ldmatrix lane mapping (x4: m0=rows0-7/k0-15, m1=rows8-15/k0-15,
    //                              m2=rows0-7/k16-31, m3=rows8-15/k16-31)
    const int rowoffA = (lane & 7) + ((lane >> 3) & 1) * 8;
    const uint32_t kparA = (uint32_t)(lane >> 4);
    // B ldmatrix lane mapping (x4: m0=n0-7/k0, m1=n0-7/k1, m2=n8-15/k0, m3=n8-15/k1)
    const int rowoffB = (lane & 7) + ((lane >> 4) & 1) * 8;
    const uint32_t kparB = (uint32_t)((lane >> 3) & 1);

    uint32_t arow[4], amask[4];
    #pragma unroll
    for (int mt = 0; mt < 4; mt++) {
        const int r = wm * 64 + mt * 16 + rowoffA;
        arow[mt]  = (uint32_t)r * 64;
        amask[mt] = (uint32_t)((r >> 1) & 3);
    }
    uint32_t brow[2], bmask[2];
    #pragma unroll
    for (int bt = 0; bt < 2; bt++) {
        const int r = wn * 32 + bt * 16 + rowoffB;
        brow[bt]  = (uint32_t)r * 64;
        bmask[bt] = (uint32_t)((r >> 1) & 3);
    }

    int P11[4][4][4] = {};
    int Pc [4][4][4] = {};

    stage_load_i8(sm0 + 0 * I8_STAGE, A1, A2, B1, B2, mb, nb, 0, tid);
    CP_COMMIT();
    stage_load_i8(sm0 + 1 * I8_STAGE, A1, A2, B1, B2, mb, nb, 64, tid);
    CP_COMMIT();

    #pragma unroll 1
    for (int s = 0; s < 12; s++) {
        if (s < 11) { CP_WAIT(1); } else { CP_WAIT(0); }
        __syncthreads();

        const uint32_t sb = sm0 + (s % 3) * I8_STAGE;
        #pragma unroll
        for (int kc = 0; kc < 2; kc++) {
            const uint32_t k2 = (uint32_t)(kc * 2);

            // B fragments (levels 1 & 2): 4 n8-tiles each
            uint32_t b1f[4][2], b2f[4][2];
            #pragma unroll
            for (int bt = 0; bt < 2; bt++) {
                const uint32_t off = brow[bt] + (((k2 + kparB) ^ bmask[bt]) << 4);
                uint32_t tmp[4];
                ldsm4(tmp, sb + XB1 + off);
                b1f[2 * bt][0] = tmp[0]; b1f[2 * bt][1] = tmp[1];
                b1f[2 * bt + 1][0] = tmp[2]; b1f[2 * bt + 1][1] = tmp[3];
                ldsm4(tmp, sb + XB2 + off);
                b2f[2 * bt][0] = tmp[0]; b2f[2 * bt][1] = tmp[1];
                b2f[2 * bt + 1][0] = tmp[2]; b2f[2 * bt + 1][1] = tmp[3];
            }

            uint32_t af[4][4];
            #pragma unroll
            for (int mt = 0; mt < 4; mt++)
                ldsm4(af[mt], sb + XA1 + arow[mt] + (((k2 + kparA) ^ amask[mt]) << 4));
            #pragma unroll
            for (int mt = 0; mt < 4; mt++)
                #pragma unroll
                for (int nt = 0; nt < 4; nt++) {
                    mma_s8(P11[mt][nt], af[mt], b1f[nt]);
                    mma_s8(Pc [mt][nt], af[mt], b2f[nt]);
                }
            #pragma unroll
            for (int mt = 0; mt < 4; mt++)
                ldsm4(af[mt], sb + XA2 + arow[mt] + (((k2 + kparA) ^ amask[mt]) << 4));
            #pragma unroll
            for (int mt = 0; mt < 4; mt++)
                #pragma unroll
                for (int nt = 0; nt < 4; nt++)
                    mma_s8(Pc[mt][nt], af[mt], b1f[nt]);
        }

        if (s + 2 < 12) {
            stage_load_i8(sm0 + ((s + 2) % 3) * I8_STAGE, A1, A2, B1, B2,
                          mb, nb, (s + 2) * 64, tid);
            CP_COMMIT();
        }
    }

    // epilogue: v = s1[m]*t1[n]*(P11 + Pc/252) + bias
    const int g  = lane >> 2;
    const int tg = lane & 3;
    constexpr float INV = 1.0f / 252.0f;
    #pragma unroll
    for (int mt = 0; mt < 4; mt++) {
        const int mrow = mb + wm * 64 + mt * 16 + g;
        const float sa0 = s1x[mrow], sa1 = s1x[mrow + 8];
        const float mk0 = mask[mrow], mk1 = mask[mrow + 8];
        #pragma unroll
        for (int nt = 0; nt < 4; nt++) {
            const int col = nb + wn * 32 + nt * 8 + tg * 2;
            const float tb0 = t1w[col], tb1 = t1w[col + 1];
            const float bs0 = bias[col], bs1 = bias[col + 1];
            float2 o0, o1;
            o0.x = epi_f(((float)P11[mt][nt][0] + (float)Pc[mt][nt][0] * INV) * sa0 * tb0 + bs0, mk0, epi);
            o0.y = epi_f(((float)P11[mt][nt][1] + (float)Pc[mt][nt][1] * INV) * sa0 * tb1 + bs1, mk0, epi);
            o1.x = epi_f(((float)P11[mt][nt][2] + (float)Pc[mt][nt][2] * INV) * sa1 * tb0 + bs0, mk1, epi);
            o1.y = epi_f(((float)P11[mt][nt][3] + (float)Pc[mt][nt][3] * INV) * sa1 * tb1 + bs1, mk1, epi);
            *reinterpret_cast<float2*>(C + (size_t)mrow * NQKV + col) = o0;
            *reinterpret_cast<float2*>(C + (size_t)(mrow + 8) * NQKV + col) = o1;
        }
    }
}

// ---------------------------------------------------------------------------
// Quantize x: per-row 2-level int8 (one warp per row)
// ---------------------------------------------------------------------------
__global__ void __launch_bounds__(256)
quant_x_kernel(const float* __restrict__ x,
               int8_t* __restrict__ a1, int8_t* __restrict__ a2,
               float* __restrict__ s1out)
{
    const int row  = blockIdx.x * 8 + (threadIdx.x >> 5);
    const int lane = threadIdx.x & 31;
    const float* xr = x + (size_t)row * 768;

    float4 v[6];
    float mx = 0.0f;
    #pragma unroll
    for (int j = 0; j < 6; j++) {
        v[j] = *reinterpret_cast<const float4*>(xr + (lane + 32 * j) * 4);
        mx = fmaxf(mx, fmaxf(fmaxf(fabsf(v[j].x), fabsf(v[j].y)),
                             fmaxf(fabsf(v[j].z), fabsf(v[j].w))));
    }
    #pragma unroll
    for (int o = 16; o > 0; o >>= 1)
        mx = fmaxf(mx, __shfl_xor_sync(0xFFFFFFFFu, mx, o));

    const float s1 = fmaxf(mx, 1e-20f) / 127.0f;
    const float i1 = 1.0f / s1;
    const float i2 = 252.0f / s1;
    if (lane == 0) s1out[row] = s1;

    #pragma unroll
    for (int j = 0; j < 6; j++) {
        const float* e = &v[j].x;
        char q1[4], q2[4];
        #pragma unroll
        for (int t = 0; t < 4; t++) {
            int c1 = __float2int_rn(e[t] * i1);
            c1 = max(-127, min(127, c1));
            const float r = e[t] - (float)c1 * s1;
            int c2 = __float2int_rn(r * i2);
            c2 = max(-127, min(127, c2));
            q1[t] = (char)c1; q2[t] = (char)c2;
        }
        const size_t o = (size_t)row * 768 + (lane + 32 * j) * 4;
        *reinterpret_cast<char4*>(a1 + o) = make_char4(q1[0], q1[1], q1[2], q1[3]);
        *reinterpret_cast<char4*>(a2 + o) = make_char4(q2[0], q2[1], q2[2], q2[3]);
    }
}

// ---------------------------------------------------------------------------
// Quantize + transpose W: out[n][k] = quant(W[k][n]), per-column scale
// grid 24 blocks of (32,8); block handles 32 columns
// ---------------------------------------------------------------------------
__global__ void __launch_bounds__(256)
quantW_kernel(const float* __restrict__ W,
              int8_t* __restrict__ b1, int8_t* __restrict__ b2,
              float* __restrict__ t1out, int noff)
{
    __shared__ float pm[8][32];
    __shared__ float scale[32];
    __shared__ float tile[32][33];

    const int n0 = blockIdx.x * 32;
    const int tx = threadIdx.x, ty = threadIdx.y;

    float mx = 0.0f;
    for (int k = ty; k < 768; k += 8)
        mx = fmaxf(mx, fabsf(W[(size_t)k * 768 + n0 + tx]));
    pm[ty][tx] = mx;
    __syncthreads();
    if (ty == 0) {
        float m = pm[0][tx];
        #pragma unroll
        for (int i = 1; i < 8; i++) m = fmaxf(m, pm[i][tx]);
        const float s = fmaxf(m, 1e-20f) / 127.0f;
        scale[tx] = s;
        t1out[noff + n0 + tx] = s;
    }
    __syncthreads();

    for (int k0 = 0; k0 < 768; k0 += 32) {
        #pragma unroll
        for (int i = 0; i < 32; i += 8)
            tile[ty + i][tx] = W[(size_t)(k0 + ty + i) * 768 + n0 + tx];
        __syncthreads();
        #pragma unroll
        for (int i = 0; i < 32; i += 8) {
            const int n = ty + i;
            const float s = scale[n];
            const float val = tile[tx][n];
            int c1 = __float2int_rn(val / s);
            c1 = max(-127, min(127, c1));
            const float r = val - (float)c1 * s;
            int c2 = __float2int_rn(r * 252.0f / s);
            c2 = max(-127, min(127, c2));
            const size_t o = (size_t)(noff + n0 + n) * 768 + k0 + tx;
            b1[o] = (char)c1;
            b2[o] = (char)c2;
        }
        __syncthreads();
    }
}

__global__ void bias_concat_kernel(const float* bq, const float* bk, const float* bv,
                                   float* out)
{
    const int i = threadIdx.x;
    const float* src = (blockIdx.x == 0) ? bq : (blockIdx.x == 1) ? bk : bv;
    out[blockIdx.x * 768 + i] = src[i];
}

// ---------------------------------------------------------------------------
// bf16-split GEMM (output projection only) — unchanged from R4
// ---------------------------------------------------------------------------
constexpr int STAGE_BYTES = 49152;
constexpr int GSMEM_BYTES = 3 * STAGE_BYTES;
constexpr int SA_HI = 0, SA_LO = 8192, SB_HI = 16384, SB_LO = 32768;

__device__ __forceinline__ void stage_load(
    uint32_t sbase,
    const __nv_bfloat16* __restrict__ Ahi, const __nv_bfloat16* __restrict__ Alo,
    const __nv_bfloat16* __restrict__ Bhi, const __nv_bfloat16* __restrict__ Blo,
    int mb, int nb, int k0, int tid)
{
    #pragma unroll
    for (int t = 0; t < 2; t++) {
        const int lin = tid + t * 256;
        const int r = lin >> 2;
        const int c = lin & 3;
        const uint32_t so = (uint32_t)r * 64 + ((uint32_t)(c ^ ((r >> 1) & 3)) << 4);
        const size_t ga = (size_t)(mb + r) * 768 + k0 + c * 8;
        cpa16(sbase + SA_HI + so, Ahi + ga);
        cpa16(sbase + SA_LO + so, Alo + ga);
    }
    #pragma unroll
    for (int t = 0; t < 4; t++) {
        const int lin = tid + t * 256;
        const int r = lin >> 2;
        const int c = lin & 3;
        const uint32_t so = (uint32_t)r * 64 + ((uint32_t)(c ^ ((r >> 1) & 3)) << 4);
        const size_t gb = (size_t)(nb + r) * 768 + k0 + c * 8;
        cpa16(sbase + SB_HI + so, Bhi + gb);
        cpa16(sbase + SB_LO + so, Blo + gb);
    }
}

__global__ void __launch_bounds__(256, 1)
gemm_tc(const __nv_bfloat16* __restrict__ Ahi, const __nv_bfloat16* __restrict__ Alo,
        const __nv_bfloat16* __restrict__ Bhi, const __nv_bfloat16* __restrict__ Blo,
        const float* __restrict__ bias, float* __restrict__ C)
{
    extern __shared__ char smraw[];
    const uint32_t sm0 = smem_u32(smraw);

    const int tid  = threadIdx.x;
    const int lane = tid & 31;
    const int warp = tid >> 5;
    const int wm = warp & 1;
    const int wn = warp >> 1;
    const int nb = blockIdx.x * 256;
    const int mb = blockIdx.y * 128;

    uint32_t baseA[4], maskA[4];
    const int arow0 = wm * 64 + (lane & 15);
    const uint32_t acs = (uint32_t)(lane >> 4);
    #pragma unroll
    for (int mt = 0; mt < 4; mt++) {
        const int r = arow0 + mt * 16;
        baseA[mt] = (uint32_t)r * 64;
        maskA[mt] = (uint32_t)((r >> 1) & 3);
    }
    uint32_t baseB[4], maskB[4];
    const int brow0 = wn * 64 + (lane & 7) + ((lane >> 4) << 3);
    const uint32_t bcs = (uint32_t)((lane >> 3) & 1);
    #pragma unroll
    for (int bt = 0; bt < 4; bt++) {
        const int r = brow0 + bt * 16;
        baseB[bt] = (uint32_t)r * 64;
        maskB[bt] = (uint32_t)((r >> 1) & 3);
    }

    float acc[4][8][4] = {};

    stage_load(sm0 + 0 * STAGE_BYTES, Ahi, Alo, Bhi, Blo, mb, nb, 0, tid);
    CP_COMMIT();
    stage_load(sm0 + 1 * STAGE_BYTES, Ahi, Alo, Bhi, Blo, mb, nb, 32, tid);
    CP_COMMIT();

    #pragma unroll 1
    for (int s = 0; s < 24; s++) {
        if (s < 23) { CP_WAIT(1); } else { CP_WAIT(0); }
        __syncthreads();

        const uint32_t sb = sm0 + (s % 3) * STAGE_BYTES;
        #pragma unroll
        for (int ks = 0; ks < 2; ks++) {
            const uint32_t kc = (uint32_t)(ks * 2);
            uint32_t bh[8][2], bl[8][2];
            #pragma unroll
            for (int bt = 0; bt < 4; bt++) {
                const uint32_t off = baseB[bt] + (((kc + bcs) ^ maskB[bt]) << 4);
                uint32_t tmp[4];
                ldsm4(tmp, sb + SB_HI + off);
                bh[2 * bt][0] = tmp[0]; bh[2 * bt][1] = tmp[1];
                bh[2 * bt + 1][0] = tmp[2]; bh[2 * bt + 1][1] = tmp[3];
                ldsm4(tmp, sb + SB_LO + off);
                bl[2 * bt][0] = tmp[0]; bl[2 * bt][1] = tmp[1];
                bl[2 * bt + 1][0] = tmp[2]; bl[2 * bt + 1][1] = tmp[3];
            }
            uint32_t a[4][4];
            #pragma unroll
            for (int mt = 0; mt < 4; mt++)
                ldsm4(a[mt], sb + SA_HI + baseA[mt] + (((kc + acs) ^ maskA[mt]) << 4));
            #pragma unroll
            for (int mt = 0; mt < 4; mt++)
                #pragma unroll
                for (int nt = 0; nt < 8; nt++) {
                    mma_bf16(acc[mt][nt], a[mt], bh[nt]);
                    mma_bf16(acc[mt][nt], a[mt], bl[nt]);
                }
            #pragma unroll
            for (int mt = 0; mt < 4; mt++)
                ldsm4(a[mt], sb + SA_LO + baseA[mt] + (((kc + acs) ^ maskA[mt]) << 4));
            #pragma unroll
            for (int mt = 0; mt < 4; mt++)
                #pragma unroll
                for (int nt = 0; nt < 8; nt++)
                    mma_bf16(acc[mt][nt], a[mt], bh[nt]);
        }

        if (s + 2 < 24) {
            stage_load(sm0 + ((s + 2) % 3) * STAGE_BYTES, Ahi, Alo, Bhi, Blo,
                       mb, nb, (s + 2) * 32, tid);
            CP_COMMIT();
        }
    }

    const int r0 = lane >> 2;
    const int c0 = (lane & 3) * 2;
    #pragma unroll
    for (int mt = 0; mt < 4; mt++) {
        const int mrow = mb + wm * 64 + mt * 16 + r0;
        #pragma unroll
        for (int nt = 0; nt < 8; nt++) {
            const int col = nb + wn * 64 + nt * 8 + c0;
            const float b0 = bias[col], b1 = bias[col + 1];
            float2 o0, o1;
            o0.x = acc[mt][nt][0] + b0;
            o0.y = acc[mt][nt][1] + b1;
            o1.x = acc[mt][nt][2] + b0;
            o1.y = acc[mt][nt][3] + b1;
            *reinterpret_cast<float2*>(C + (size_t)mrow * 768 + col) = o0;
            *reinterpret_cast<float2*>(C + (size_t)(mrow + 8) * 768 + col) = o1;
        }
    }
}

// Prep: transpose + split Wo (bf16 hi/lo)
__global__ void __launch_bounds__(256)
wsplit_kernel(const float* __restrict__ W,
              __nv_bfloat16* __restrict__ hi, __nv_bfloat16* __restrict__ lo)
{
    __shared__ float t[32][33];
    const int bx = blockIdx.x * 32, by = blockIdx.y * 32;
    const int tx = threadIdx.x, ty = threadIdx.y;
    #pragma unroll
    for (int i = 0; i < 32; i += 8)
        t[ty + i][tx] = W[(size_t)(by + ty + i) * 768 + bx + tx];
    __syncthreads();
    #pragma unroll
    for (int i = 0; i < 32; i += 8) {
        const float v = t[tx][ty + i];
        const __nv_bfloat16 h = __float2bfloat16(v);
        const __nv_bfloat16 l = __float2bfloat16(v - __bfloat162float(h));
        const size_t o = (size_t)(bx + ty + i) * 768 + by + tx;
        hi[o] = h; lo[o] = l;
    }
}

// ---------------------------------------------------------------------------
// Attention core (fp32) — strides adjusted for merged g_qkv [M, 2304]
// ---------------------------------------------------------------------------
__global__ void __launch_bounds__(256)
kv_part_kernel(const float* __restrict__ QKV)
{
    __shared__ float Ks[64][64];
    __shared__ float Vs[64][64];

    const int bh = blockIdx.x;
    const int ch = blockIdx.y;
    const int b = bh / Hh, h = bh % Hh;
    const int tid = threadIdx.x;
    const int d  = tid >> 2;
    const int e0 = (tid & 3) * 16;

    float acc[16] = {};
    float ks = 0.0f;

    const int sbeg = ch * (Ss / 4), send = sbeg + (Ss / 4);
    for (int s0 = sbeg; s0 < send; s0 += 64) {
        #pragma unroll
        for (int i = 0; i < 4; i++) {
            const int lin = tid + i * 256;
            const int r = lin >> 4;
            const int c = (lin & 15) * 4;
            const size_t off = ((size_t)(b * Ss + s0 + r)) * NQKV + h * 64 + c;
            *reinterpret_cast<float4*>(&Ks[r][c]) = *reinterpret_cast<const float4*>(QKV + off + 768);
            *reinterpret_cast<float4*>(&Vs[r][c]) = *reinterpret_cast<const float4*>(QKV + off + 1536);
        }
        __syncthreads();

        #pragma unroll 4
        for (int s = 0; s < 64; s++) {
            const float kval = Ks[s][d];
            #pragma unroll
            for (int j = 0; j < 16; j++)
                acc[j] = fmaf(kval, Vs[s][e0 + j], acc[j]);
        }
        if (tid < 64) {
            #pragma unroll 4
            for (int s = 0; s < 64; s++) ks += Ks[s][tid];
        }
        __syncthreads();
    }

    #pragma unroll
    for (int j = 0; j < 16; j++) g_kvp[ch][bh][d * 64 + e0 + j] = acc[j];
    if (tid < 64) g_ksp[ch][bh][tid] = ks;
}

__global__ void __launch_bounds__(256)
kv_reduce_kernel()
{
    const int bh = blockIdx.x;
    const int tid = threadIdx.x;
    #pragma unroll
    for (int j = 0; j < 16; j++) {
        const int idx = tid * 16 + j;
        g_kv[(size_t)bh * 4096 + idx] =
            g_kvp[0][bh][idx] + g_kvp[1][bh][idx] + g_kvp[2][bh][idx] + g_kvp[3][bh][idx];
    }
    if (tid < 64)
        g_ksum[bh * 64 + tid] = g_ksp[0][bh][tid] + g_ksp[1][bh][tid]
                              + g_ksp[2][bh][tid] + g_ksp[3][bh][tid];
}

__global__ void __launch_bounds__(256)
attn_apply_kernel(const float* __restrict__ QKV,
                  __nv_bfloat16* __restrict__ Ohi, __nv_bfloat16* __restrict__ Olo)
{
    __shared__ float kvS[64][64];
    __shared__ float ksS[64];
    __shared__ float qS[4][64];

    const int bh = blockIdx.x;
    const int b = bh / Hh, h = bh % Hh;
    const int tid = threadIdx.x;

    #pragma unroll
    for (int i = 0; i < 4; i++) {
        const int lin = tid + i * 256;
        const int r = lin >> 4;
        const int c = (lin & 15) * 4;
        *reinterpret_cast<float4*>(&kvS[r][c]) =
            *reinterpret_cast<const float4*>(&g_kv[((size_t)bh * 64 + r) * 64 + c]);
    }
    if (tid < 16)
        *reinterpret_cast<float4*>(&ksS[tid * 4]) =
            *reinterpret_cast<const float4*>(&g_ksum[bh * 64 + tid * 4]);
    __syncthreads();

    const int e  = tid & 63;
    const int rr = tid >> 6;

    for (int it = 0; it < 16; it++) {
        const int s = blockIdx.y * 64 + it * 4 + rr;
        qS[rr][e] = QKV[((size_t)(b * Ss + s)) * NQKV + h * 64 + e];
        __syncthreads();

        float num = 0.0f, den = 0.0f;
        #pragma unroll
        for (int dd = 0; dd < 64; dd++) {
            const float qv = qS[rr][dd];
            num = fmaf(qv, kvS[dd][e], num);
            den = fmaf(qv, ksS[dd], den);
        }
        const float r = num / den;
        const __nv_bfloat16 hh = __float2bfloat16(r);
        const size_t oo = ((size_t)(b * Ss + s)) * 768 + h * 64 + e;
        Ohi[oo] = hh;
        Olo[oo] = __float2bfloat16(r - __bfloat162float(hh));
        __syncthreads();
    }
}

// ---------------------------------------------------------------------------
extern "C" void kernel_launch(void* const* d_in, const int* in_sizes, int n_in,
                              void* d_out, int out_size)
{
    const float* x    = (const float*)d_in[0];
    const float* mask = (const float*)d_in[1];
    const float* Wq   = (const float*)d_in[2];
    const float* bq   = (const float*)d_in[3];
    const float* Wk   = (const float*)d_in[4];
    const float* bk   = (const float*)d_in[5];
    const float* Wv   = (const float*)d_in[6];
    const float* bv   = (const float*)d_in[7];
    const float* Wo   = (const float*)d_in[8];
    const float* bo   = (const float*)d_in[9];
    float* out = (float*)d_out;

    float *qkv, *s1x, *t1w, *biasc;
    int8_t *x8a, *x8b, *w8a, *w8b;
    __nv_bfloat16 *ahi, *alo, *whi, *wlo;
    cudaGetSymbolAddress((void**)&qkv,  g_qkv);
    cudaGetSymbolAddress((void**)&x8a,  g_x8a);
    cudaGetSymbolAddress((void**)&x8b,  g_x8b);
    cudaGetSymbolAddress((void**)&s1x,  g_s1x);
    cudaGetSymbolAddress((void**)&w8a,  g_w8a);
    cudaGetSymbolAddress((void**)&w8b,  g_w8b);
    cudaGetSymbolAddress((void**)&t1w,  g_t1w);
    cudaGetSymbolAddress((void**)&biasc,g_biasc);
    cudaGetSymbolAddress((void**)&ahi,  g_ahi);
    cudaGetSymbolAddress((void**)&alo,  g_alo);
    cudaGetSymbolAddress((void**)&whi,  g_whi);
    cudaGetSymbolAddress((void**)&wlo,  g_wlo);

    cudaFuncSetAttribute(gemm_i8, cudaFuncAttributeMaxDynamicSharedMemorySize, I8_SMEM);
    cudaFuncSetAttribute(gemm_tc, cudaFuncAttributeMaxDynamicSharedMemorySize, GSMEM_BYTES);

    // prep
    quant_x_kernel<<<M / 8, 256>>>(x, x8a, x8b, s1x);
    quantW_kernel<<<24, dim3(32, 8)>>>(Wq, w8a, w8b, t1w, 0);
    quantW_kernel<<<24, dim3(32, 8)>>>(Wk, w8a, w8b, t1w, 768);
    quantW_kernel<<<24, dim3(32, 8)>>>(Wv, w8a, w8b, t1w, 1536);
    bias_concat_kernel<<<3, 768>>>(bq, bk, bv, biasc);
    wsplit_kernel<<<dim3(24, 24), dim3(32, 8)>>>(Wo, whi, wlo);

    // QKV projections: one merged int8 tensor-core GEMM
    gemm_i8<<<dim3(18, 512), 256, I8_SMEM>>>(x8a, x8b, w8a, w8b,
                                             s1x, t1w, biasc, mask, qkv);

    // linear-attention core (fp32)
    kv_part_kernel<<<dim3(Bb * Hh, 4), 256>>>(qkv);
    kv_reduce_kernel<<<Bb * Hh, 256>>>();
    attn_apply_kernel<<<dim3(Bb * Hh, Ss / 64), 256>>>(qkv, ahi, alo);

    // output projection (bf16 split tensor core)
    gemm_tc<<<dim3(3, 512), 256, GSMEM_BYTES>>>(ahi, alo, whi, wlo, bo, out);
}

// round 6
// speedup vs baseline: 2.1394x; 2.1394x over previous
#include <cuda_runtime.h>
#include <cuda_fp16.h>
#include <math.h>
#include <stdint.h>

// Problem constants
#define Bb   16
#define Ss   4096
#define Hh   12
#define Dd   64
constexpr int M = Bb * Ss;   // 65536
constexpr int NQKV = 2304;   // merged Q|K|V columns

// ---------------------------------------------------------------------------
// Scratch (device globals)
// ---------------------------------------------------------------------------
__device__ float  g_qkv[(size_t)M * NQKV];        // Q | K | V fp32
__device__ __half g_xh[(size_t)M * 768];          // x fp16
__device__ __half g_a16[(size_t)M * 768];         // attention output fp16
__device__ __half g_wh[(size_t)NQKV * 768];       // Wqkv^T fp16 hi
__device__ __half g_wl[(size_t)NQKV * 768];       // Wqkv^T fp16 lo
__device__ __half g_woh[768 * 768];               // Wo^T hi
__device__ __half g_wol[768 * 768];               // Wo^T lo
__device__ float  g_biasc[NQKV];
__device__ float  g_kv[Bb * Hh * Dd * Dd];
__device__ float  g_ksum[Bb * Hh * Dd];
__device__ float  g_kvp[4][Bb * Hh][Dd * Dd];
__device__ float  g_ksp[4][Bb * Hh][Dd];

// ---------------------------------------------------------------------------
// PTX helpers (sm_80-compatible: cp.async, ldmatrix, mma.sync)
// ---------------------------------------------------------------------------
__device__ __forceinline__ uint32_t smem_u32(const void* p) {
    uint32_t a;
    asm("{ .reg .u64 t; cvta.to.shared.u64 t, %1; cvt.u32.u64 %0, t; }"
        : "=r"(a) : "l"(p));
    return a;
}

__device__ __forceinline__ void cpa16(uint32_t dst, const void* src) {
    asm volatile("cp.async.cg.shared.global [%0], [%1], 16;" :: "r"(dst), "l"(src) : "memory");
}
#define CP_COMMIT() asm volatile("cp.async.commit_group;" ::: "memory")
#define CP_WAIT(n)  asm volatile("cp.async.wait_group %0;" :: "n"(n) : "memory")

__device__ __forceinline__ void ldsm4(uint32_t* r, uint32_t addr) {
    asm volatile("ldmatrix.sync.aligned.m8n8.x4.shared.b16 {%0,%1,%2,%3}, [%4];"
                 : "=r"(r[0]), "=r"(r[1]), "=r"(r[2]), "=r"(r[3]) : "r"(addr));
}

__device__ __forceinline__ void mma_f16(float* c, const uint32_t* a, const uint32_t* b) {
    asm volatile(
        "mma.sync.aligned.m16n8k16.row.col.f32.f16.f16.f32 "
        "{%0,%1,%2,%3}, {%4,%5,%6,%7}, {%8,%9}, {%0,%1,%2,%3};"
        : "+f"(c[0]), "+f"(c[1]), "+f"(c[2]), "+f"(c[3])
        : "r"(a[0]), "r"(a[1]), "r"(a[2]), "r"(a[3]), "r"(b[0]), "r"(b[1]));
}

__device__ __forceinline__ float epi_f(float v, float mk, int epi) {
    if (epi >= 1) v *= mk;
    if (epi == 2) { v = (v > 0.0f) ? (v + 1.0f) : expf(v); v *= 0.125f; }
    return v;
}

// ---------------------------------------------------------------------------
// fp16 2-term GEMM:  C = A(fp16) @ (Bhi + Blo)^T   (B pre-transposed [N][K])
// CTA tile 128x256x32, warp tile 64x64, 3-stage cp.async pipeline.
// Smem/stage: A 8K | Bh 16K | Bl 16K = 40KB. XOR swizzle on 16B chunks.
// mode 1 (QKV): ldC=2304, epi = (bx<6 ? elu : mask-only), bias=concat
// mode 0 (out): ldC=768,  epi = plain bias
// ---------------------------------------------------------------------------
constexpr int F_STAGE = 40960;
constexpr int F_SMEM  = 3 * F_STAGE;
constexpr int FA = 0, FBH = 8192, FBL = 24576;

__device__ __forceinline__ void stage_load_f16(
    uint32_t sbase,
    const __half* __restrict__ A,
    const __half* __restrict__ Bh, const __half* __restrict__ Bl,
    int mb, int nb, int k0, int tid)
{
    // A: 128 rows x 4 chunks = 512 slots
    #pragma unroll
    for (int t = 0; t < 2; t++) {
        const int lin = tid + t * 256;
        const int r = lin >> 2;
        const int c = lin & 3;
        const uint32_t so = (uint32_t)r * 64 + ((uint32_t)(c ^ ((r >> 1) & 3)) << 4);
        cpa16(sbase + FA + so, A + (size_t)(mb + r) * 768 + k0 + c * 8);
    }
    // B: 256 rows x 4 chunks = 1024 slots (hi and lo)
    #pragma unroll
    for (int t = 0; t < 4; t++) {
        const int lin = tid + t * 256;
        const int r = lin >> 2;
        const int c = lin & 3;
        const uint32_t so = (uint32_t)r * 64 + ((uint32_t)(c ^ ((r >> 1) & 3)) << 4);
        const size_t gb = (size_t)(nb + r) * 768 + k0 + c * 8;
        cpa16(sbase + FBH + so, Bh + gb);
        cpa16(sbase + FBL + so, Bl + gb);
    }
}

__global__ void __launch_bounds__(256, 1)
gemm_f16(const __half* __restrict__ A,
         const __half* __restrict__ Bh, const __half* __restrict__ Bl,
         const float* __restrict__ bias, const float* __restrict__ mask,
         float* __restrict__ C, int ldC, int mode)
{
    extern __shared__ char smraw[];
    const uint32_t sm0 = smem_u32(smraw);

    const int tid  = threadIdx.x;
    const int lane = tid & 31;
    const int warp = tid >> 5;
    const int wm = warp & 1;        // 2 warps in M -> 64 rows
    const int wn = warp >> 1;       // 4 warps in N -> 64 cols
    const int nb = blockIdx.x * 256;
    const int mb = blockIdx.y * 128;
    const int epi = (mode == 0) ? 0 : ((blockIdx.x < 6) ? 2 : 1);

    // per-lane ldmatrix addressing
    uint32_t baseA[4], maskA[4];
    const int arow0 = wm * 64 + (lane & 15);
    const uint32_t acs = (uint32_t)(lane >> 4);
    #pragma unroll
    for (int mt = 0; mt < 4; mt++) {
        const int r = arow0 + mt * 16;
        baseA[mt] = (uint32_t)r * 64;
        maskA[mt] = (uint32_t)((r >> 1) & 3);
    }
    uint32_t baseB[4], maskB[4];
    const int brow0 = wn * 64 + (lane & 7) + ((lane >> 4) << 3);
    const uint32_t bcs = (uint32_t)((lane >> 3) & 1);
    #pragma unroll
    for (int bt = 0; bt < 4; bt++) {
        const int r = brow0 + bt * 16;
        baseB[bt] = (uint32_t)r * 64;
        maskB[bt] = (uint32_t)((r >> 1) & 3);
    }

    float acc[4][8][4] = {};

    stage_load_f16(sm0 + 0 * F_STAGE, A, Bh, Bl, mb, nb, 0, tid);
    CP_COMMIT();
    stage_load_f16(sm0 + 1 * F_STAGE, A, Bh, Bl, mb, nb, 32, tid);
    CP_COMMIT();

    #pragma unroll 1
    for (int s = 0; s < 24; s++) {
        if (s < 23) { CP_WAIT(1); } else { CP_WAIT(0); }
        __syncthreads();

        const uint32_t sb = sm0 + (s % 3) * F_STAGE;
        #pragma unroll
        for (int ks = 0; ks < 2; ks++) {
            const uint32_t kc = (uint32_t)(ks * 2);

            uint32_t bh[8][2], bl[8][2];
            #pragma unroll
            for (int bt = 0; bt < 4; bt++) {
                const uint32_t off = baseB[bt] + (((kc + bcs) ^ maskB[bt]) << 4);
                uint32_t tmp[4];
                ldsm4(tmp, sb + FBH + off);
                bh[2 * bt][0] = tmp[0]; bh[2 * bt][1] = tmp[1];
                bh[2 * bt + 1][0] = tmp[2]; bh[2 * bt + 1][1] = tmp[3];
                ldsm4(tmp, sb + FBL + off);
                bl[2 * bt][0] = tmp[0]; bl[2 * bt][1] = tmp[1];
                bl[2 * bt + 1][0] = tmp[2]; bl[2 * bt + 1][1] = tmp[3];
            }

            uint32_t a[4][4];
            #pragma unroll
            for (int mt = 0; mt < 4; mt++)
                ldsm4(a[mt], sb + FA + baseA[mt] + (((kc + acs) ^ maskA[mt]) << 4));

            #pragma unroll
            for (int mt = 0; mt < 4; mt++)
                #pragma unroll
                for (int nt = 0; nt < 8; nt++) {
                    mma_f16(acc[mt][nt], a[mt], bh[nt]);
                    mma_f16(acc[mt][nt], a[mt], bl[nt]);
                }
        }

        if (s + 2 < 24) {
            stage_load_f16(sm0 + ((s + 2) % 3) * F_STAGE, A, Bh, Bl,
                           mb, nb, (s + 2) * 32, tid);
            CP_COMMIT();
        }
    }

    // epilogue
    const int r0 = lane >> 2;
    const int c0 = (lane & 3) * 2;
    #pragma unroll
    for (int mt = 0; mt < 4; mt++) {
        const int mrow = mb + wm * 64 + mt * 16 + r0;
        const float mk0 = (epi >= 1) ? mask[mrow] : 1.0f;
        const float mk1 = (epi >= 1) ? mask[mrow + 8] : 1.0f;
        #pragma unroll
        for (int nt = 0; nt < 8; nt++) {
            const int col = nb + wn * 64 + nt * 8 + c0;
            const float b0 = bias[col], b1 = bias[col + 1];
            float2 o0, o1;
            o0.x = epi_f(acc[mt][nt][0] + b0, mk0, epi);
            o0.y = epi_f(acc[mt][nt][1] + b1, mk0, epi);
            o1.x = epi_f(acc[mt][nt][2] + b0, mk1, epi);
            o1.y = epi_f(acc[mt][nt][3] + b1, mk1, epi);
            *reinterpret_cast<float2*>(C + (size_t)mrow * ldC + col) = o0;
            *reinterpret_cast<float2*>(C + (size_t)(mrow + 8) * ldC + col) = o1;
        }
    }
}

// ---------------------------------------------------------------------------
// Prep kernels
// ---------------------------------------------------------------------------
__global__ void __launch_bounds__(256)
cvt_x_kernel(const float* __restrict__ x, __half* __restrict__ xh)
{
    const size_t i = ((size_t)blockIdx.x * 256 + threadIdx.x) * 8;
    const float4 v0 = *reinterpret_cast<const float4*>(x + i);
    const float4 v1 = *reinterpret_cast<const float4*>(x + i + 4);
    __half2 h[4];
    h[0] = __floats2half2_rn(v0.x, v0.y);
    h[1] = __floats2half2_rn(v0.z, v0.w);
    h[2] = __floats2half2_rn(v1.x, v1.y);
    h[3] = __floats2half2_rn(v1.z, v1.w);
    *reinterpret_cast<uint4*>(xh + i) = *reinterpret_cast<uint4*>(h);
}

// transpose + fp16 hi/lo split:  out[noff+n][k] = split(W[k][n])
__global__ void __launch_bounds__(256)
wsplit16_kernel(const float* __restrict__ W,
                __half* __restrict__ hi, __half* __restrict__ lo, int noff)
{
    __shared__ float t[32][33];
    const int bx = blockIdx.x * 32, by = blockIdx.y * 32;
    const int tx = threadIdx.x, ty = threadIdx.y;   // 32 x 8
    #pragma unroll
    for (int i = 0; i < 32; i += 8)
        t[ty + i][tx] = W[(size_t)(by + ty + i) * 768 + bx + tx];
    __syncthreads();
    #pragma unroll
    for (int i = 0; i < 32; i += 8) {
        const float v = t[tx][ty + i];
        const __half h = __float2half(v);
        const __half l = __float2half(v - __half2float(h));
        const size_t o = (size_t)(noff + bx + ty + i) * 768 + by + tx;
        hi[o] = h; lo[o] = l;
    }
}

__global__ void bias_concat_kernel(const float* bq, const float* bk, const float* bv,
                                   float* out)
{
    const int i = threadIdx.x;
    const float* src = (blockIdx.x == 0) ? bq : (blockIdx.x == 1) ? bk : bv;
    out[blockIdx.x * 768 + i] = src[i];
}

// ---------------------------------------------------------------------------
// Attention core (fp32) — reads merged g_qkv [M, 2304]
// ---------------------------------------------------------------------------
__global__ void __launch_bounds__(256)
kv_part_kernel(const float* __restrict__ QKV)
{
    __shared__ float Ks[64][64];
    __shared__ float Vs[64][64];

    const int bh = blockIdx.x;
    const int ch = blockIdx.y;
    const int b = bh / Hh, h = bh % Hh;
    const int tid = threadIdx.x;
    const int d  = tid >> 2;
    const int e0 = (tid & 3) * 16;

    float acc[16] = {};
    float ks = 0.0f;

    const int sbeg = ch * (Ss / 4), send = sbeg + (Ss / 4);
    for (int s0 = sbeg; s0 < send; s0 += 64) {
        #pragma unroll
        for (int i = 0; i < 4; i++) {
            const int lin = tid + i * 256;
            const int r = lin >> 4;
            const int c = (lin & 15) * 4;
            const size_t off = ((size_t)(b * Ss + s0 + r)) * NQKV + h * 64 + c;
            *reinterpret_cast<float4*>(&Ks[r][c]) = *reinterpret_cast<const float4*>(QKV + off + 768);
            *reinterpret_cast<float4*>(&Vs[r][c]) = *reinterpret_cast<const float4*>(QKV + off + 1536);
        }
        __syncthreads();

        #pragma unroll 4
        for (int s = 0; s < 64; s++) {
            const float kval = Ks[s][d];
            #pragma unroll
            for (int j = 0; j < 16; j++)
                acc[j] = fmaf(kval, Vs[s][e0 + j], acc[j]);
        }
        if (tid < 64) {
            #pragma unroll 4
            for (int s = 0; s < 64; s++) ks += Ks[s][tid];
        }
        __syncthreads();
    }

    #pragma unroll
    for (int j = 0; j < 16; j++) g_kvp[ch][bh][d * 64 + e0 + j] = acc[j];
    if (tid < 64) g_ksp[ch][bh][tid] = ks;
}

__global__ void __launch_bounds__(256)
kv_reduce_kernel()
{
    const int bh = blockIdx.x;
    const int tid = threadIdx.x;
    #pragma unroll
    for (int j = 0; j < 16; j++) {
        const int idx = tid * 16 + j;
        g_kv[(size_t)bh * 4096 + idx] =
            g_kvp[0][bh][idx] + g_kvp[1][bh][idx] + g_kvp[2][bh][idx] + g_kvp[3][bh][idx];
    }
    if (tid < 64)
        g_ksum[bh * 64 + tid] = g_ksp[0][bh][tid] + g_ksp[1][bh][tid]
                              + g_ksp[2][bh][tid] + g_ksp[3][bh][tid];
}

__global__ void __launch_bounds__(256)
attn_apply_kernel(const float* __restrict__ QKV, __half* __restrict__ O16)
{
    __shared__ float kvS[64][64];
    __shared__ float ksS[64];
    __shared__ float qS[4][64];

    const int bh = blockIdx.x;
    const int b = bh / Hh, h = bh % Hh;
    const int tid = threadIdx.x;

    #pragma unroll
    for (int i = 0; i < 4; i++) {
        const int lin = tid + i * 256;
        const int r = lin >> 4;
        const int c = (lin & 15) * 4;
        *reinterpret_cast<float4*>(&kvS[r][c]) =
            *reinterpret_cast<const float4*>(&g_kv[((size_t)bh * 64 + r) * 64 + c]);
    }
    if (tid < 16)
        *reinterpret_cast<float4*>(&ksS[tid * 4]) =
            *reinterpret_cast<const float4*>(&g_ksum[bh * 64 + tid * 4]);
    __syncthreads();

    const int e  = tid & 63;
    const int rr = tid >> 6;

    for (int it = 0; it < 16; it++) {
        const int s = blockIdx.y * 64 + it * 4 + rr;
        qS[rr][e] = QKV[((size_t)(b * Ss + s)) * NQKV + h * 64 + e];
        __syncthreads();

        float num = 0.0f, den = 0.0f;
        #pragma unroll
        for (int dd = 0; dd < 64; dd++) {
            const float qv = qS[rr][dd];
            num = fmaf(qv, kvS[dd][e], num);
            den = fmaf(qv, ksS[dd], den);
        }
        O16[((size_t)(b * Ss + s)) * 768 + h * 64 + e] = __float2half(num / den);
        __syncthreads();
    }
}

// ---------------------------------------------------------------------------
extern "C" void kernel_launch(void* const* d_in, const int* in_sizes, int n_in,
                              void* d_out, int out_size)
{
    const float* x    = (const float*)d_in[0];
    const float* mask = (const float*)d_in[1];
    const float* Wq   = (const float*)d_in[2];
    const float* bq   = (const float*)d_in[3];
    const float* Wk   = (const float*)d_in[4];
    const float* bk   = (const float*)d_in[5];
    const float* Wv   = (const float*)d_in[6];
    const float* bv   = (const float*)d_in[7];
    const float* Wo   = (const float*)d_in[8];
    const float* bo   = (const float*)d_in[9];
    float* out = (float*)d_out;

    float *qkv, *biasc;
    __half *xh, *a16, *wh, *wl, *woh, *wol;
    cudaGetSymbolAddress((void**)&qkv,   g_qkv);
    cudaGetSymbolAddress((void**)&xh,    g_xh);
    cudaGetSymbolAddress((void**)&a16,   g_a16);
    cudaGetSymbolAddress((void**)&wh,    g_wh);
    cudaGetSymbolAddress((void**)&wl,    g_wl);
    cudaGetSymbolAddress((void**)&woh,   g_woh);
    cudaGetSymbolAddress((void**)&wol,   g_wol);
    cudaGetSymbolAddress((void**)&biasc, g_biasc);

    cudaFuncSetAttribute(gemm_f16, cudaFuncAttributeMaxDynamicSharedMemorySize, F_SMEM);

    const dim3 wgrid(24, 24), wblk(32, 8);

    // prep
    cvt_x_kernel<<<(int)(((size_t)M * 768) / 8 / 256), 256>>>(x, xh);
    wsplit16_kernel<<<wgrid, wblk>>>(Wq, wh, wl, 0);
    wsplit16_kernel<<<wgrid, wblk>>>(Wk, wh, wl, 768);
    wsplit16_kernel<<<wgrid, wblk>>>(Wv, wh, wl, 1536);
    wsplit16_kernel<<<wgrid, wblk>>>(Wo, woh, wol, 0);
    bias_concat_kernel<<<3, 768>>>(bq, bk, bv, biasc);

    // merged QKV projection (fp16 2-term tensor core)
    gemm_f16<<<dim3(9, 512), 256, F_SMEM>>>(xh, wh, wl, biasc, mask, qkv, NQKV, 1);

    // linear-attention core (fp32)
    kv_part_kernel<<<dim3(Bb * Hh, 4), 256>>>(qkv);
    kv_reduce_kernel<<<Bb * Hh, 256>>>();
    attn_apply_kernel<<<dim3(Bb * Hh, Ss / 64), 256>>>(qkv, a16);

    // output projection (fp16 2-term tensor core)
    gemm_f16<<<dim3(3, 512), 256, F_SMEM>>>(a16, woh, wol, bo, mask, out, 768, 0);
}

// round 7
// speedup vs baseline: 3.7259x; 1.7416x over previous
#include <cuda_runtime.h>
#include <cuda_fp16.h>
#include <math.h>
#include <stdint.h>

// Problem constants
#define Bb   16
#define Ss   4096
#define Hh   12
#define Dd   64
constexpr int M = Bb * Ss;   // 65536
constexpr int NQKV = 2304;   // merged Q|K|V columns

// ---------------------------------------------------------------------------
// Scratch (device globals)
// ---------------------------------------------------------------------------
__device__ __half g_qkv16[(size_t)M * NQKV];      // Q | K | V fp16
__device__ __half g_xh[(size_t)M * 768];          // x fp16
__device__ __half g_a16[(size_t)M * 768];         // attention output fp16
__device__ __half g_wh[(size_t)NQKV * 768];       // Wqkv^T fp16 hi
__device__ __half g_wl[(size_t)NQKV * 768];       // Wqkv^T fp16 lo
__device__ __half g_woh[768 * 768];               // Wo^T hi
__device__ __half g_wol[768 * 768];               // Wo^T lo
__device__ float  g_biasc[NQKV];
__device__ float  g_kvp[4][Bb * Hh][64 * 72];     // kv partials (fp32)
__device__ __half g_kvt[Bb * Hh][64 * 72];        // reduced kv+ksum (fp16)

// ---------------------------------------------------------------------------
// PTX helpers (sm_80-compatible: cp.async, ldmatrix, mma.sync)
// ---------------------------------------------------------------------------
__device__ __forceinline__ uint32_t smem_u32(const void* p) {
    uint32_t a;
    asm("{ .reg .u64 t; cvta.to.shared.u64 t, %1; cvt.u32.u64 %0, t; }"
        : "=r"(a) : "l"(p));
    return a;
}

__device__ __forceinline__ void cpa16(uint32_t dst, const void* src) {
    asm volatile("cp.async.cg.shared.global [%0], [%1], 16;" :: "r"(dst), "l"(src) : "memory");
}
#define CP_COMMIT() asm volatile("cp.async.commit_group;" ::: "memory")
#define CP_WAIT(n)  asm volatile("cp.async.wait_group %0;" :: "n"(n) : "memory")

__device__ __forceinline__ void ldsm4(uint32_t* r, uint32_t addr) {
    asm volatile("ldmatrix.sync.aligned.m8n8.x4.shared.b16 {%0,%1,%2,%3}, [%4];"
                 : "=r"(r[0]), "=r"(r[1]), "=r"(r[2]), "=r"(r[3]) : "r"(addr));
}
__device__ __forceinline__ void ldsm4t(uint32_t* r, uint32_t addr) {
    asm volatile("ldmatrix.sync.aligned.m8n8.x4.trans.shared.b16 {%0,%1,%2,%3}, [%4];"
                 : "=r"(r[0]), "=r"(r[1]), "=r"(r[2]), "=r"(r[3]) : "r"(addr));
}
__device__ __forceinline__ void ldsm2t(uint32_t* r, uint32_t addr) {
    asm volatile("ldmatrix.sync.aligned.m8n8.x2.trans.shared.b16 {%0,%1}, [%2];"
                 : "=r"(r[0]), "=r"(r[1]) : "r"(addr));
}

__device__ __forceinline__ void mma_f16(float* c, const uint32_t* a, const uint32_t* b) {
    asm volatile(
        "mma.sync.aligned.m16n8k16.row.col.f32.f16.f16.f32 "
        "{%0,%1,%2,%3}, {%4,%5,%6,%7}, {%8,%9}, {%0,%1,%2,%3};"
        : "+f"(c[0]), "+f"(c[1]), "+f"(c[2]), "+f"(c[3])
        : "r"(a[0]), "r"(a[1]), "r"(a[2]), "r"(a[3]), "r"(b[0]), "r"(b[1]));
}

__device__ __forceinline__ float epi_f(float v, float mk, int epi) {
    if (epi >= 1) v *= mk;
    if (epi == 2) { v = (v > 0.0f) ? (v + 1.0f) : expf(v); v *= 0.125f; }
    return v;
}

// ---------------------------------------------------------------------------
// fp16 2-term GEMM:  C = A(fp16) @ (Bhi + Blo)^T   (B pre-transposed [N][K])
// CTA tile 128x256x32, warp tile 64x64, 3-stage cp.async.
// mode 1 (QKV): writes fp16 to C16 (ld 2304); epi elu for bx<6, mask for rest
// mode 0 (out): writes fp32 to C32 (ld 768); plain bias
// ---------------------------------------------------------------------------
constexpr int F_STAGE = 40960;
constexpr int F_SMEM  = 3 * F_STAGE;
constexpr int FA = 0, FBH = 8192, FBL = 24576;

__device__ __forceinline__ void stage_load_f16(
    uint32_t sbase,
    const __half* __restrict__ A,
    const __half* __restrict__ Bh, const __half* __restrict__ Bl,
    int mb, int nb, int k0, int tid)
{
    #pragma unroll
    for (int t = 0; t < 2; t++) {
        const int lin = tid + t * 256;
        const int r = lin >> 2;
        const int c = lin & 3;
        const uint32_t so = (uint32_t)r * 64 + ((uint32_t)(c ^ ((r >> 1) & 3)) << 4);
        cpa16(sbase + FA + so, A + (size_t)(mb + r) * 768 + k0 + c * 8);
    }
    #pragma unroll
    for (int t = 0; t < 4; t++) {
        const int lin = tid + t * 256;
        const int r = lin >> 2;
        const int c = lin & 3;
        const uint32_t so = (uint32_t)r * 64 + ((uint32_t)(c ^ ((r >> 1) & 3)) << 4);
        const size_t gb = (size_t)(nb + r) * 768 + k0 + c * 8;
        cpa16(sbase + FBH + so, Bh + gb);
        cpa16(sbase + FBL + so, Bl + gb);
    }
}

__global__ void __launch_bounds__(256, 1)
gemm_f16(const __half* __restrict__ A,
         const __half* __restrict__ Bh, const __half* __restrict__ Bl,
         const float* __restrict__ bias, const float* __restrict__ mask,
         float* __restrict__ C32, __half* __restrict__ C16, int mode)
{
    extern __shared__ char smraw[];
    const uint32_t sm0 = smem_u32(smraw);

    const int tid  = threadIdx.x;
    const int lane = tid & 31;
    const int warp = tid >> 5;
    const int wm = warp & 1;
    const int wn = warp >> 1;
    const int nb = blockIdx.x * 256;
    const int mb = blockIdx.y * 128;
    const int epi = (mode == 0) ? 0 : ((blockIdx.x < 6) ? 2 : 1);

    uint32_t baseA[4], maskA[4];
    const int arow0 = wm * 64 + (lane & 15);
    const uint32_t acs = (uint32_t)(lane >> 4);
    #pragma unroll
    for (int mt = 0; mt < 4; mt++) {
        const int r = arow0 + mt * 16;
        baseA[mt] = (uint32_t)r * 64;
        maskA[mt] = (uint32_t)((r >> 1) & 3);
    }
    uint32_t baseB[4], maskB[4];
    const int brow0 = wn * 64 + (lane & 7) + ((lane >> 4) << 3);
    const uint32_t bcs = (uint32_t)((lane >> 3) & 1);
    #pragma unroll
    for (int bt = 0; bt < 4; bt++) {
        const int r = brow0 + bt * 16;
        baseB[bt] = (uint32_t)r * 64;
        maskB[bt] = (uint32_t)((r >> 1) & 3);
    }

    float acc[4][8][4] = {};

    stage_load_f16(sm0 + 0 * F_STAGE, A, Bh, Bl, mb, nb, 0, tid);
    CP_COMMIT();
    stage_load_f16(sm0 + 1 * F_STAGE, A, Bh, Bl, mb, nb, 32, tid);
    CP_COMMIT();

    #pragma unroll 1
    for (int s = 0; s < 24; s++) {
        if (s < 23) { CP_WAIT(1); } else { CP_WAIT(0); }
        __syncthreads();

        const uint32_t sb = sm0 + (s % 3) * F_STAGE;
        #pragma unroll
        for (int ks = 0; ks < 2; ks++) {
            const uint32_t kc = (uint32_t)(ks * 2);
            uint32_t bh[8][2], bl[8][2];
            #pragma unroll
            for (int bt = 0; bt < 4; bt++) {
                const uint32_t off = baseB[bt] + (((kc + bcs) ^ maskB[bt]) << 4);
                uint32_t tmp[4];
                ldsm4(tmp, sb + FBH + off);
                bh[2 * bt][0] = tmp[0]; bh[2 * bt][1] = tmp[1];
                bh[2 * bt + 1][0] = tmp[2]; bh[2 * bt + 1][1] = tmp[3];
                ldsm4(tmp, sb + FBL + off);
                bl[2 * bt][0] = tmp[0]; bl[2 * bt][1] = tmp[1];
                bl[2 * bt + 1][0] = tmp[2]; bl[2 * bt + 1][1] = tmp[3];
            }
            uint32_t a[4][4];
            #pragma unroll
            for (int mt = 0; mt < 4; mt++)
                ldsm4(a[mt], sb + FA + baseA[mt] + (((kc + acs) ^ maskA[mt]) << 4));
            #pragma unroll
            for (int mt = 0; mt < 4; mt++)
                #pragma unroll
                for (int nt = 0; nt < 8; nt++) {
                    mma_f16(acc[mt][nt], a[mt], bh[nt]);
                    mma_f16(acc[mt][nt], a[mt], bl[nt]);
                }
        }

        if (s + 2 < 24) {
            stage_load_f16(sm0 + ((s + 2) % 3) * F_STAGE, A, Bh, Bl,
                           mb, nb, (s + 2) * 32, tid);
            CP_COMMIT();
        }
    }

    const int r0 = lane >> 2;
    const int c0 = (lane & 3) * 2;
    #pragma unroll
    for (int mt = 0; mt < 4; mt++) {
        const int mrow = mb + wm * 64 + mt * 16 + r0;
        const float mk0 = (epi >= 1) ? mask[mrow] : 1.0f;
        const float mk1 = (epi >= 1) ? mask[mrow + 8] : 1.0f;
        #pragma unroll
        for (int nt = 0; nt < 8; nt++) {
            const int col = nb + wn * 64 + nt * 8 + c0;
            const float b0 = bias[col], b1 = bias[col + 1];
            const float v00 = epi_f(acc[mt][nt][0] + b0, mk0, epi);
            const float v01 = epi_f(acc[mt][nt][1] + b1, mk0, epi);
            const float v10 = epi_f(acc[mt][nt][2] + b0, mk1, epi);
            const float v11 = epi_f(acc[mt][nt][3] + b1, mk1, epi);
            if (mode == 1) {
                *reinterpret_cast<__half2*>(C16 + (size_t)mrow * NQKV + col) =
                    __floats2half2_rn(v00, v01);
                *reinterpret_cast<__half2*>(C16 + (size_t)(mrow + 8) * NQKV + col) =
                    __floats2half2_rn(v10, v11);
            } else {
                *reinterpret_cast<float2*>(C32 + (size_t)mrow * 768 + col) =
                    make_float2(v00, v01);
                *reinterpret_cast<float2*>(C32 + (size_t)(mrow + 8) * 768 + col) =
                    make_float2(v10, v11);
            }
        }
    }
}

// ---------------------------------------------------------------------------
// Prep kernels
// ---------------------------------------------------------------------------
__global__ void __launch_bounds__(256)
cvt_x_kernel(const float* __restrict__ x, __half* __restrict__ xh)
{
    const size_t i = ((size_t)blockIdx.x * 256 + threadIdx.x) * 8;
    const float4 v0 = *reinterpret_cast<const float4*>(x + i);
    const float4 v1 = *reinterpret_cast<const float4*>(x + i + 4);
    __half2 h[4];
    h[0] = __floats2half2_rn(v0.x, v0.y);
    h[1] = __floats2half2_rn(v0.z, v0.w);
    h[2] = __floats2half2_rn(v1.x, v1.y);
    h[3] = __floats2half2_rn(v1.z, v1.w);
    *reinterpret_cast<uint4*>(xh + i) = *reinterpret_cast<uint4*>(h);
}

__global__ void __launch_bounds__(256)
wsplit16_kernel(const float* __restrict__ W,
                __half* __restrict__ hi, __half* __restrict__ lo, int noff)
{
    __shared__ float t[32][33];
    const int bx = blockIdx.x * 32, by = blockIdx.y * 32;
    const int tx = threadIdx.x, ty = threadIdx.y;
    #pragma unroll
    for (int i = 0; i < 32; i += 8)
        t[ty + i][tx] = W[(size_t)(by + ty + i) * 768 + bx + tx];
    __syncthreads();
    #pragma unroll
    for (int i = 0; i < 32; i += 8) {
        const float v = t[tx][ty + i];
        const __half h = __float2half(v);
        const __half l = __float2half(v - __half2float(h));
        const size_t o = (size_t)(noff + bx + ty + i) * 768 + by + tx;
        hi[o] = h; lo[o] = l;
    }
}

__global__ void bias_concat_kernel(const float* bq, const float* bk, const float* bv,
                                   float* out)
{
    const int i = threadIdx.x;
    const float* src = (blockIdx.x == 0) ? bq : (blockIdx.x == 1) ? bk : bv;
    out[blockIdx.x * 768 + i] = src[i];
}

// ---------------------------------------------------------------------------
// kv = K^T V (+ ksum in col 64) via fp16 tensor cores.
// grid (192, 4): one (b,h) x 1024-seq chunk per block, 128 threads.
// V smem tile padded to 72 cols: col64 = 1 (-> ksum), 65-71 = 0.
// Warp w owns d-rows [16w, 16w+16); full N=72 (9 n8-tiles); K = 1024.
// ---------------------------------------------------------------------------
__global__ void __launch_bounds__(128)
kv_tc_kernel(const __half* __restrict__ QKV16)
{
    __shared__ __half kb[2][64][72];
    __shared__ __half vb[2][64][72];

    const int bh = blockIdx.x, ch = blockIdx.y;
    const int b = bh / Hh, h = bh % Hh;
    const int tid = threadIdx.x, lane = tid & 31, warp = tid >> 5;

    // init V pad cols (never overwritten by cp.async)
    {
        const int bf = tid >> 6, r = tid & 63;
        vb[bf][r][64] = __float2half(1.0f);
        #pragma unroll
        for (int c = 65; c < 72; c++) vb[bf][r][c] = __float2half(0.0f);
    }
    __syncthreads();

    const int chunk0 = ch * 1024;
    const int d0 = warp * 16;

    // tile loader: 64 seq rows of K and V (8 x 16B chunks per row)
    #define KV_LOAD(st, s0)                                                       \
        do {                                                                      \
            _Pragma("unroll")                                                     \
            for (int t = 0; t < 4; t++) {                                         \
                const int lin = tid + t * 128;                                    \
                const int r = lin >> 3, c = lin & 7;                              \
                const size_t base =                                               \
                    ((size_t)(b * Ss + (s0) + r)) * NQKV + h * 64 + c * 8;        \
                cpa16(smem_u32(&kb[st][r][c * 8]), QKV16 + base + 768);           \
                cpa16(smem_u32(&vb[st][r][c * 8]), QKV16 + base + 1536);          \
            }                                                                     \
            CP_COMMIT();                                                          \
        } while (0)

    float acc[9][4] = {};

    KV_LOAD(0, chunk0);
    KV_LOAD(1, chunk0 + 64);

    const int g = lane >> 3, l = lane & 7;

    #pragma unroll 1
    for (int it = 0; it < 16; it++) {
        if (it < 15) { CP_WAIT(1); } else { CP_WAIT(0); }
        __syncthreads();

        const int st = it & 1;
        #pragma unroll
        for (int ks = 0; ks < 4; ks++) {
            // A = K^T fragment (trans): rows s, cols d
            const int srow = ks * 16 + ((g & 2) ? 8 : 0) + l;
            const int scol = d0 + ((g & 1) ? 8 : 0);
            uint32_t a[4];
            ldsm4t(a, smem_u32(&kb[st][srow][scol]));

            uint32_t bfrag[9][2];
            const int vrow = ks * 16 + ((g & 1) ? 8 : 0) + l;
            #pragma unroll
            for (int np = 0; np < 4; np++) {
                const int vcol = np * 16 + ((g & 2) ? 8 : 0);
                uint32_t t4[4];
                ldsm4t(t4, smem_u32(&vb[st][vrow][vcol]));
                bfrag[2 * np][0] = t4[0];     bfrag[2 * np][1] = t4[1];
                bfrag[2 * np + 1][0] = t4[2]; bfrag[2 * np + 1][1] = t4[3];
            }
            {   // 9th tile (cols 64-71, x2 uses lanes 0-15)
                const int vr2 = ks * 16 + ((lane >> 3) & 1) * 8 + l;
                uint32_t t2[2];
                ldsm2t(t2, smem_u32(&vb[st][vr2][64]));
                bfrag[8][0] = t2[0]; bfrag[8][1] = t2[1];
            }
            #pragma unroll
            for (int nt = 0; nt < 9; nt++) mma_f16(acc[nt], a, bfrag[nt]);
        }
        __syncthreads();
        if (it + 2 < 16) KV_LOAD(st, chunk0 + (it + 2) * 64);
    }
    #undef KV_LOAD

    // write fp32 partial: rows d0+lane/4 (+8), cols nt*8 + (lane%4)*2
    float* dst = &g_kvp[ch][bh][0];
    const int r = lane >> 2, cp = (lane & 3) * 2;
    #pragma unroll
    for (int nt = 0; nt < 9; nt++) {
        const int col = nt * 8 + cp;
        *reinterpret_cast<float2*>(dst + (d0 + r) * 72 + col) =
            make_float2(acc[nt][0], acc[nt][1]);
        *reinterpret_cast<float2*>(dst + (d0 + r + 8) * 72 + col) =
            make_float2(acc[nt][2], acc[nt][3]);
    }
}

__global__ void __launch_bounds__(128)
kv_reduce_kernel()
{
    const int bh = blockIdx.x;
    for (int i = threadIdx.x; i < 64 * 72; i += 128) {
        const float s = g_kvp[0][bh][i] + g_kvp[1][bh][i]
                      + g_kvp[2][bh][i] + g_kvp[3][bh][i];
        g_kvt[bh][i] = __float2half(s);
    }
}

// ---------------------------------------------------------------------------
// num|den = Q @ kv[64x72] (col 64 = den); out = num/den -> fp16 a16.
// grid (192, 16): one (b,h) x 256-seq rows per block, 128 threads.
// ---------------------------------------------------------------------------
__global__ void __launch_bounds__(128)
num_tc_kernel(const __half* __restrict__ QKV16, __half* __restrict__ A16)
{
    __shared__ __half kvs[64][72];

    const int bh = blockIdx.x;
    const int b = bh / Hh, h = bh % Hh;
    const int tid = threadIdx.x, lane = tid & 31, warp = tid >> 5;
    const int s0 = blockIdx.y * 256;

    {
        const uint32_t* src = reinterpret_cast<const uint32_t*>(&g_kvt[bh][0]);
        uint32_t* dst = reinterpret_cast<uint32_t*>(&kvs[0][0]);
        for (int i = tid; i < 64 * 72 / 2; i += 128) dst[i] = src[i];
    }
    __syncthreads();

    // B fragments for all 4 k-steps x 9 n-tiles (kv is row-major [d][e] -> trans)
    uint32_t bfr[4][9][2];
    const int g = lane >> 3, l = lane & 7;
    #pragma unroll
    for (int ks = 0; ks < 4; ks++) {
        const int vrow = ks * 16 + ((g & 1) ? 8 : 0) + l;
        #pragma unroll
        for (int np = 0; np < 4; np++) {
            const int vcol = np * 16 + ((g & 2) ? 8 : 0);
            uint32_t t4[4];
            ldsm4t(t4, smem_u32(&kvs[vrow][vcol]));
            bfr[ks][2 * np][0] = t4[0];     bfr[ks][2 * np][1] = t4[1];
            bfr[ks][2 * np + 1][0] = t4[2]; bfr[ks][2 * np + 1][1] = t4[3];
        }
        const int vr2 = ks * 16 + ((lane >> 3) & 1) * 8 + l;
        uint32_t t2[2];
        ldsm2t(t2, smem_u32(&kvs[vr2][64]));
        bfr[ks][8][0] = t2[0]; bfr[ks][8][1] = t2[1];
    }

    const uint32_t* Q32 = reinterpret_cast<const uint32_t*>(QKV16);
    const int rbase = b * Ss + s0 + warp * 64;

    #pragma unroll 1
    for (int mt = 0; mt < 4; mt++) {
        float acc[9][4] = {};
        const int row = rbase + mt * 16 + (lane >> 2);
        #pragma unroll
        for (int ks = 0; ks < 4; ks++) {
            const int cb = h * 64 + ks * 16 + (lane & 3) * 2;
            uint32_t a[4];
            a[0] = Q32[((size_t)row * NQKV + cb) >> 1];
            a[1] = Q32[((size_t)(row + 8) * NQKV + cb) >> 1];
            a[2] = Q32[((size_t)row * NQKV + cb + 8) >> 1];
            a[3] = Q32[((size_t)(row + 8) * NQKV + cb + 8) >> 1];
            #pragma unroll
            for (int nt = 0; nt < 9; nt++) mma_f16(acc[nt], a, bfr[ks][nt]);
        }

        const float den0 = __shfl_sync(0xFFFFFFFFu, acc[8][0], lane & 28);
        const float den1 = __shfl_sync(0xFFFFFFFFu, acc[8][2], lane & 28);
        const float i0 = 1.0f / den0, i1 = 1.0f / den1;
        #pragma unroll
        for (int nt = 0; nt < 8; nt++) {
            const int col = h * 64 + nt * 8 + (lane & 3) * 2;
            *reinterpret_cast<__half2*>(A16 + (size_t)row * 768 + col) =
                __floats2half2_rn(acc[nt][0] * i0, acc[nt][1] * i0);
            *reinterpret_cast<__half2*>(A16 + (size_t)(row + 8) * 768 + col) =
                __floats2half2_rn(acc[nt][2] * i1, acc[nt][3] * i1);
        }
    }
}

// ---------------------------------------------------------------------------
extern "C" void kernel_launch(void* const* d_in, const int* in_sizes, int n_in,
                              void* d_out, int out_size)
{
    const float* x    = (const float*)d_in[0];
    const float* mask = (const float*)d_in[1];
    const float* Wq   = (const float*)d_in[2];
    const float* bq   = (const float*)d_in[3];
    const float* Wk   = (const float*)d_in[4];
    const float* bk   = (const float*)d_in[5];
    const float* Wv   = (const float*)d_in[6];
    const float* bv   = (const float*)d_in[7];
    const float* Wo   = (const float*)d_in[8];
    const float* bo   = (const float*)d_in[9];
    float* out = (float*)d_out;

    float *biasc;
    __half *qkv16, *xh, *a16, *wh, *wl, *woh, *wol;
    cudaGetSymbolAddress((void**)&qkv16, g_qkv16);
    cudaGetSymbolAddress((void**)&xh,    g_xh);
    cudaGetSymbolAddress((void**)&a16,   g_a16);
    cudaGetSymbolAddress((void**)&wh,    g_wh);
    cudaGetSymbolAddress((void**)&wl,    g_wl);
    cudaGetSymbolAddress((void**)&woh,   g_woh);
    cudaGetSymbolAddress((void**)&wol,   g_wol);
    cudaGetSymbolAddress((void**)&biasc, g_biasc);

    cudaFuncSetAttribute(gemm_f16, cudaFuncAttributeMaxDynamicSharedMemorySize, F_SMEM);

    const dim3 wgrid(24, 24), wblk(32, 8);

    // prep
    cvt_x_kernel<<<(int)(((size_t)M * 768) / 8 / 256), 256>>>(x, xh);
    wsplit16_kernel<<<wgrid, wblk>>>(Wq, wh, wl, 0);
    wsplit16_kernel<<<wgrid, wblk>>>(Wk, wh, wl, 768);
    wsplit16_kernel<<<wgrid, wblk>>>(Wv, wh, wl, 1536);
    wsplit16_kernel<<<wgrid, wblk>>>(Wo, woh, wol, 0);
    bias_concat_kernel<<<3, 768>>>(bq, bk, bv, biasc);

    // merged QKV projection -> fp16
    gemm_f16<<<dim3(9, 512), 256, F_SMEM>>>(xh, wh, wl, biasc, mask,
                                            nullptr, qkv16, 1);

    // linear-attention core (tensor cores)
    kv_tc_kernel<<<dim3(Bb * Hh, 4), 128>>>(qkv16);
    kv_reduce_kernel<<<Bb * Hh, 128>>>();
    num_tc_kernel<<<dim3(Bb * Hh, Ss / 256), 128>>>(qkv16, a16);

    // output projection -> fp32 d_out
    gemm_f16<<<dim3(3, 512), 256, F_SMEM>>>(a16, woh, wol, bo, mask,
                                            out, nullptr, 0);
}

// round 8
// speedup vs baseline: 4.5416x; 1.2189x over previous
#include <cuda_runtime.h>
#include <cuda_fp16.h>
#include <math.h>
#include <stdint.h>

// Problem constants
#define Bb   16
#define Ss   4096
#define Hh   12
#define Dd   64
constexpr int M = Bb * Ss;   // 65536
constexpr int NQKV = 2304;   // merged Q|K|V columns

// ---------------------------------------------------------------------------
// Scratch (device globals)
// ---------------------------------------------------------------------------
__device__ __half g_qkv16[(size_t)M * NQKV];      // Q | K | V fp16
__device__ __half g_xh[(size_t)M * 768];          // x fp16
__device__ __half g_a16[(size_t)M * 768];         // attention output fp16
__device__ __half g_wh[(size_t)NQKV * 768];       // Wqkv^T fp16 hi
__device__ __half g_wl[(size_t)NQKV * 768];       // Wqkv^T fp16 lo
__device__ __half g_woh[768 * 768];               // Wo^T hi
__device__ __half g_wol[768 * 768];               // Wo^T lo
__device__ float  g_biasc[NQKV];
__device__ float  g_kvp[4][Bb * Hh][64 * 72];     // kv partials (fp32)
__device__ __half g_kvt[Bb * Hh][64 * 72];        // reduced kv+ksum (fp16)

// ---------------------------------------------------------------------------
// PTX helpers (sm_80-compatible: cp.async, ldmatrix, mma.sync)
// ---------------------------------------------------------------------------
__device__ __forceinline__ uint32_t smem_u32(const void* p) {
    uint32_t a;
    asm("{ .reg .u64 t; cvta.to.shared.u64 t, %1; cvt.u32.u64 %0, t; }"
        : "=r"(a) : "l"(p));
    return a;
}

__device__ __forceinline__ void cpa16(uint32_t dst, const void* src) {
    asm volatile("cp.async.cg.shared.global [%0], [%1], 16;" :: "r"(dst), "l"(src) : "memory");
}
#define CP_COMMIT() asm volatile("cp.async.commit_group;" ::: "memory")
#define CP_WAIT(n)  asm volatile("cp.async.wait_group %0;" :: "n"(n) : "memory")

__device__ __forceinline__ void ldsm4(uint32_t* r, uint32_t addr) {
    asm volatile("ldmatrix.sync.aligned.m8n8.x4.shared.b16 {%0,%1,%2,%3}, [%4];"
                 : "=r"(r[0]), "=r"(r[1]), "=r"(r[2]), "=r"(r[3]) : "r"(addr));
}
__device__ __forceinline__ void ldsm4t(uint32_t* r, uint32_t addr) {
    asm volatile("ldmatrix.sync.aligned.m8n8.x4.trans.shared.b16 {%0,%1,%2,%3}, [%4];"
                 : "=r"(r[0]), "=r"(r[1]), "=r"(r[2]), "=r"(r[3]) : "r"(addr));
}
__device__ __forceinline__ void ldsm2t(uint32_t* r, uint32_t addr) {
    asm volatile("ldmatrix.sync.aligned.m8n8.x2.trans.shared.b16 {%0,%1}, [%2];"
                 : "=r"(r[0]), "=r"(r[1]) : "r"(addr));
}

__device__ __forceinline__ void mma_f16(float* c, const uint32_t* a, const uint32_t* b) {
    asm volatile(
        "mma.sync.aligned.m16n8k16.row.col.f32.f16.f16.f32 "
        "{%0,%1,%2,%3}, {%4,%5,%6,%7}, {%8,%9}, {%0,%1,%2,%3};"
        : "+f"(c[0]), "+f"(c[1]), "+f"(c[2]), "+f"(c[3])
        : "r"(a[0]), "r"(a[1]), "r"(a[2]), "r"(a[3]), "r"(b[0]), "r"(b[1]));
}

__device__ __forceinline__ float epi_f(float v, float mk, int epi) {
    if (epi >= 1) v *= mk;
    if (epi == 2) { v = (v > 0.0f) ? (v + 1.0f) : expf(v); v *= 0.125f; }
    return v;
}

// ---------------------------------------------------------------------------
// fp16 2-term GEMM:  C = A(fp16) @ (Bhi + Blo)^T   (B pre-transposed [N][K])
// CTA tile 128x128x32, warp tile 64x32, 3-stage cp.async, 2 CTAs/SM.
// Smem/stage: A 8K | Bh 8K | Bl 8K = 24KB. XOR swizzle on 16B chunks.
// mode 1 (QKV): writes fp16 to C16 (ld 2304); epi elu for bx<12, mask else
// mode 0 (out): writes fp32 to C32 (ld 768); plain bias
// ---------------------------------------------------------------------------
constexpr int F_STAGE = 24576;
constexpr int F_SMEM  = 3 * F_STAGE;
constexpr int FA = 0, FBH = 8192, FBL = 16384;

__device__ __forceinline__ void stage_load_f16(
    uint32_t sbase,
    const __half* __restrict__ A,
    const __half* __restrict__ Bh, const __half* __restrict__ Bl,
    int mb, int nb, int k0, int tid)
{
    #pragma unroll
    for (int t = 0; t < 2; t++) {
        const int lin = tid + t * 256;   // 512 slots: 128 rows x 4 chunks
        const int r = lin >> 2;
        const int c = lin & 3;
        const uint32_t so = (uint32_t)r * 64 + ((uint32_t)(c ^ ((r >> 1) & 3)) << 4);
        cpa16(sbase + FA + so, A + (size_t)(mb + r) * 768 + k0 + c * 8);
        const size_t gb = (size_t)(nb + r) * 768 + k0 + c * 8;
        cpa16(sbase + FBH + so, Bh + gb);
        cpa16(sbase + FBL + so, Bl + gb);
    }
}

__global__ void __launch_bounds__(256, 2)
gemm_f16(const __half* __restrict__ A,
         const __half* __restrict__ Bh, const __half* __restrict__ Bl,
         const float* __restrict__ bias, const float* __restrict__ mask,
         float* __restrict__ C32, __half* __restrict__ C16, int mode)
{
    extern __shared__ char smraw[];
    const uint32_t sm0 = smem_u32(smraw);

    const int tid  = threadIdx.x;
    const int lane = tid & 31;
    const int warp = tid >> 5;
    const int wm = warp & 1;        // 2 warps in M -> 64 rows
    const int wn = warp >> 1;       // 4 warps in N -> 32 cols
    const int nb = blockIdx.x * 128;
    const int mb = blockIdx.y * 128;
    const int epi = (mode == 0) ? 0 : ((blockIdx.x < 12) ? 2 : 1);

    // A ldmatrix addressing (x4 over m16 x k16)
    uint32_t baseA[4], maskA[4];
    const int arow0 = wm * 64 + (lane & 15);
    const uint32_t acs = (uint32_t)(lane >> 4);
    #pragma unroll
    for (int mt = 0; mt < 4; mt++) {
        const int r = arow0 + mt * 16;
        baseA[mt] = (uint32_t)r * 64;
        maskA[mt] = (uint32_t)((r >> 1) & 3);
    }
    // B ldmatrix addressing (x4 over n16 x k16) — 2 tiles cover 32 cols
    uint32_t baseB[2], maskB[2];
    const int brow0 = wn * 32 + (lane & 7) + ((lane >> 4) << 3);
    const uint32_t bcs = (uint32_t)((lane >> 3) & 1);
    #pragma unroll
    for (int bt = 0; bt < 2; bt++) {
        const int r = brow0 + bt * 16;
        baseB[bt] = (uint32_t)r * 64;
        maskB[bt] = (uint32_t)((r >> 1) & 3);
    }

    float acc[4][4][4] = {};

    stage_load_f16(sm0 + 0 * F_STAGE, A, Bh, Bl, mb, nb, 0, tid);
    CP_COMMIT();
    stage_load_f16(sm0 + 1 * F_STAGE, A, Bh, Bl, mb, nb, 32, tid);
    CP_COMMIT();

    #pragma unroll 1
    for (int s = 0; s < 24; s++) {
        if (s < 23) { CP_WAIT(1); } else { CP_WAIT(0); }
        __syncthreads();

        const uint32_t sb = sm0 + (s % 3) * F_STAGE;
        #pragma unroll
        for (int ks = 0; ks < 2; ks++) {
            const uint32_t kc = (uint32_t)(ks * 2);

            uint32_t bh[4][2], bl[4][2];
            #pragma unroll
            for (int bt = 0; bt < 2; bt++) {
                const uint32_t off = baseB[bt] + (((kc + bcs) ^ maskB[bt]) << 4);
                uint32_t tmp[4];
                ldsm4(tmp, sb + FBH + off);
                bh[2 * bt][0] = tmp[0]; bh[2 * bt][1] = tmp[1];
                bh[2 * bt + 1][0] = tmp[2]; bh[2 * bt + 1][1] = tmp[3];
                ldsm4(tmp, sb + FBL + off);
                bl[2 * bt][0] = tmp[0]; bl[2 * bt][1] = tmp[1];
                bl[2 * bt + 1][0] = tmp[2]; bl[2 * bt + 1][1] = tmp[3];
            }
            uint32_t a[4][4];
            #pragma unroll
            for (int mt = 0; mt < 4; mt++)
                ldsm4(a[mt], sb + FA + baseA[mt] + (((kc + acs) ^ maskA[mt]) << 4));

            #pragma unroll
            for (int mt = 0; mt < 4; mt++)
                #pragma unroll
                for (int nt = 0; nt < 4; nt++) {
                    mma_f16(acc[mt][nt], a[mt], bh[nt]);
                    mma_f16(acc[mt][nt], a[mt], bl[nt]);
                }
        }

        if (s + 2 < 24) {
            stage_load_f16(sm0 + ((s + 2) % 3) * F_STAGE, A, Bh, Bl,
                           mb, nb, (s + 2) * 32, tid);
            CP_COMMIT();
        }
    }

    // epilogue
    const int r0 = lane >> 2;
    const int c0 = (lane & 3) * 2;
    #pragma unroll
    for (int mt = 0; mt < 4; mt++) {
        const int mrow = mb + wm * 64 + mt * 16 + r0;
        const float mk0 = (epi >= 1) ? mask[mrow] : 1.0f;
        const float mk1 = (epi >= 1) ? mask[mrow + 8] : 1.0f;
        #pragma unroll
        for (int nt = 0; nt < 4; nt++) {
            const int col = nb + wn * 32 + nt * 8 + c0;
            const float b0 = bias[col], b1 = bias[col + 1];
            const float v00 = epi_f(acc[mt][nt][0] + b0, mk0, epi);
            const float v01 = epi_f(acc[mt][nt][1] + b1, mk0, epi);
            const float v10 = epi_f(acc[mt][nt][2] + b0, mk1, epi);
            const float v11 = epi_f(acc[mt][nt][3] + b1, mk1, epi);
            if (mode == 1) {
                *reinterpret_cast<__half2*>(C16 + (size_t)mrow * NQKV + col) =
                    __floats2half2_rn(v00, v01);
                *reinterpret_cast<__half2*>(C16 + (size_t)(mrow + 8) * NQKV + col) =
                    __floats2half2_rn(v10, v11);
            } else {
                *reinterpret_cast<float2*>(C32 + (size_t)mrow * 768 + col) =
                    make_float2(v00, v01);
                *reinterpret_cast<float2*>(C32 + (size_t)(mrow + 8) * 768 + col) =
                    make_float2(v10, v11);
            }
        }
    }
}

// ---------------------------------------------------------------------------
// Prep kernels
// ---------------------------------------------------------------------------
__global__ void __launch_bounds__(256)
cvt_x_kernel(const float* __restrict__ x, __half* __restrict__ xh)
{
    const size_t i = ((size_t)blockIdx.x * 256 + threadIdx.x) * 8;
    const float4 v0 = *reinterpret_cast<const float4*>(x + i);
    const float4 v1 = *reinterpret_cast<const float4*>(x + i + 4);
    __half2 h[4];
    h[0] = __floats2half2_rn(v0.x, v0.y);
    h[1] = __floats2half2_rn(v0.z, v0.w);
    h[2] = __floats2half2_rn(v1.x, v1.y);
    h[3] = __floats2half2_rn(v1.z, v1.w);
    *reinterpret_cast<uint4*>(xh + i) = *reinterpret_cast<uint4*>(h);
}

__global__ void __launch_bounds__(256)
wsplit16_kernel(const float* __restrict__ W,
                __half* __restrict__ hi, __half* __restrict__ lo, int noff)
{
    __shared__ float t[32][33];
    const int bx = blockIdx.x * 32, by = blockIdx.y * 32;
    const int tx = threadIdx.x, ty = threadIdx.y;
    #pragma unroll
    for (int i = 0; i < 32; i += 8)
        t[ty + i][tx] = W[(size_t)(by + ty + i) * 768 + bx + tx];
    __syncthreads();
    #pragma unroll
    for (int i = 0; i < 32; i += 8) {
        const float v = t[tx][ty + i];
        const __half h = __float2half(v);
        const __half l = __float2half(v - __half2float(h));
        const size_t o = (size_t)(noff + bx + ty + i) * 768 + by + tx;
        hi[o] = h; lo[o] = l;
    }
}

__global__ void bias_concat_kernel(const float* bq, const float* bk, const float* bv,
                                   float* out)
{
    const int i = threadIdx.x;
    const float* src = (blockIdx.x == 0) ? bq : (blockIdx.x == 1) ? bk : bv;
    out[blockIdx.x * 768 + i] = src[i];
}

// ---------------------------------------------------------------------------
// kv = K^T V (+ ksum in col 64) via fp16 tensor cores.
// grid (192, 4): one (b,h) x 1024-seq chunk per block, 128 threads.
// ---------------------------------------------------------------------------
__global__ void __launch_bounds__(128)
kv_tc_kernel(const __half* __restrict__ QKV16)
{
    __shared__ __half kb[2][64][72];
    __shared__ __half vb[2][64][72];

    const int bh = blockIdx.x, ch = blockIdx.y;
    const int b = bh / Hh, h = bh % Hh;
    const int tid = threadIdx.x, lane = tid & 31, warp = tid >> 5;

    {
        const int bf = tid >> 6, r = tid & 63;
        vb[bf][r][64] = __float2half(1.0f);
        #pragma unroll
        for (int c = 65; c < 72; c++) vb[bf][r][c] = __float2half(0.0f);
    }
    __syncthreads();

    const int chunk0 = ch * 1024;
    const int d0 = warp * 16;

    #define KV_LOAD(st, s0)                                                       \
        do {                                                                      \
            _Pragma("unroll")                                                     \
            for (int t = 0; t < 4; t++) {                                         \
                const int lin = tid + t * 128;                                    \
                const int r = lin >> 3, c = lin & 7;                              \
                const size_t base =                                               \
                    ((size_t)(b * Ss + (s0) + r)) * NQKV + h * 64 + c * 8;        \
                cpa16(smem_u32(&kb[st][r][c * 8]), QKV16 + base + 768);           \
                cpa16(smem_u32(&vb[st][r][c * 8]), QKV16 + base + 1536);          \
            }                                                                     \
            CP_COMMIT();                                                          \
        } while (0)

    float acc[9][4] = {};

    KV_LOAD(0, chunk0);
    KV_LOAD(1, chunk0 + 64);

    const int g = lane >> 3, l = lane & 7;

    #pragma unroll 1
    for (int it = 0; it < 16; it++) {
        if (it < 15) { CP_WAIT(1); } else { CP_WAIT(0); }
        __syncthreads();

        const int st = it & 1;
        #pragma unroll
        for (int ks = 0; ks < 4; ks++) {
            const int srow = ks * 16 + ((g & 2) ? 8 : 0) + l;
            const int scol = d0 + ((g & 1) ? 8 : 0);
            uint32_t a[4];
            ldsm4t(a, smem_u32(&kb[st][srow][scol]));

            uint32_t bfrag[9][2];
            const int vrow = ks * 16 + ((g & 1) ? 8 : 0) + l;
            #pragma unroll
            for (int np = 0; np < 4; np++) {
                const int vcol = np * 16 + ((g & 2) ? 8 : 0);
                uint32_t t4[4];
                ldsm4t(t4, smem_u32(&vb[st][vrow][vcol]));
                bfrag[2 * np][0] = t4[0];     bfrag[2 * np][1] = t4[1];
                bfrag[2 * np + 1][0] = t4[2]; bfrag[2 * np + 1][1] = t4[3];
            }
            {
                const int vr2 = ks * 16 + ((lane >> 3) & 1) * 8 + l;
                uint32_t t2[2];
                ldsm2t(t2, smem_u32(&vb[st][vr2][64]));
                bfrag[8][0] = t2[0]; bfrag[8][1] = t2[1];
            }
            #pragma unroll
            for (int nt = 0; nt < 9; nt++) mma_f16(acc[nt], a, bfrag[nt]);
        }
        __syncthreads();
        if (it + 2 < 16) KV_LOAD(st, chunk0 + (it + 2) * 64);
    }
    #undef KV_LOAD

    float* dst = &g_kvp[ch][bh][0];
    const int r = lane >> 2, cp = (lane & 3) * 2;
    #pragma unroll
    for (int nt = 0; nt < 9; nt++) {
        const int col = nt * 8 + cp;
        *reinterpret_cast<float2*>(dst + (d0 + r) * 72 + col) =
            make_float2(acc[nt][0], acc[nt][1]);
        *reinterpret_cast<float2*>(dst + (d0 + r + 8) * 72 + col) =
            make_float2(acc[nt][2], acc[nt][3]);
    }
}

__global__ void __launch_bounds__(128)
kv_reduce_kernel()
{
    const int bh = blockIdx.x;
    for (int i = threadIdx.x; i < 64 * 72; i += 128) {
        const float s = g_kvp[0][bh][i] + g_kvp[1][bh][i]
                      + g_kvp[2][bh][i] + g_kvp[3][bh][i];
        g_kvt[bh][i] = __float2half(s);
    }
}

// ---------------------------------------------------------------------------
// num|den = Q @ kv[64x72] (col 64 = den); out = num/den -> fp16 a16.
// ---------------------------------------------------------------------------
__global__ void __launch_bounds__(128)
num_tc_kernel(const __half* __restrict__ QKV16, __half* __restrict__ A16)
{
    __shared__ __half kvs[64][72];

    const int bh = blockIdx.x;
    const int b = bh / Hh, h = bh % Hh;
    const int tid = threadIdx.x, lane = tid & 31, warp = tid >> 5;
    const int s0 = blockIdx.y * 256;

    {
        const uint32_t* src = reinterpret_cast<const uint32_t*>(&g_kvt[bh][0]);
        uint32_t* dst = reinterpret_cast<uint32_t*>(&kvs[0][0]);
        for (int i = tid; i < 64 * 72 / 2; i += 128) dst[i] = src[i];
    }
    __syncthreads();

    uint32_t bfr[4][9][2];
    const int g = lane >> 3, l = lane & 7;
    #pragma unroll
    for (int ks = 0; ks < 4; ks++) {
        const int vrow = ks * 16 + ((g & 1) ? 8 : 0) + l;
        #pragma unroll
        for (int np = 0; np < 4; np++) {
            const int vcol = np * 16 + ((g & 2) ? 8 : 0);
            uint32_t t4[4];
            ldsm4t(t4, smem_u32(&kvs[vrow][vcol]));
            bfr[ks][2 * np][0] = t4[0];     bfr[ks][2 * np][1] = t4[1];
            bfr[ks][2 * np + 1][0] = t4[2]; bfr[ks][2 * np + 1][1] = t4[3];
        }
        const int vr2 = ks * 16 + ((lane >> 3) & 1) * 8 + l;
        uint32_t t2[2];
        ldsm2t(t2, smem_u32(&kvs[vr2][64]));
        bfr[ks][8][0] = t2[0]; bfr[ks][8][1] = t2[1];
    }

    const uint32_t* Q32 = reinterpret_cast<const uint32_t*>(QKV16);
    const int rbase = b * Ss + s0 + warp * 64;

    #pragma unroll 1
    for (int mt = 0; mt < 4; mt++) {
        float acc[9][4] = {};
        const int row = rbase + mt * 16 + (lane >> 2);
        #pragma unroll
        for (int ks = 0; ks < 4; ks++) {
            const int cb = h * 64 + ks * 16 + (lane & 3) * 2;
            uint32_t a[4];
            a[0] = Q32[((size_t)row * NQKV + cb) >> 1];
            a[1] = Q32[((size_t)(row + 8) * NQKV + cb) >> 1];
            a[2] = Q32[((size_t)row * NQKV + cb + 8) >> 1];
            a[3] = Q32[((size_t)(row + 8) * NQKV + cb + 8) >> 1];
            #pragma unroll
            for (int nt = 0; nt < 9; nt++) mma_f16(acc[nt], a, bfr[ks][nt]);
        }

        const float den0 = __shfl_sync(0xFFFFFFFFu, acc[8][0], lane & 28);
        const float den1 = __shfl_sync(0xFFFFFFFFu, acc[8][2], lane & 28);
        const float i0 = 1.0f / den0, i1 = 1.0f / den1;
        #pragma unroll
        for (int nt = 0; nt < 8; nt++) {
            const int col = h * 64 + nt * 8 + (lane & 3) * 2;
            *reinterpret_cast<__half2*>(A16 + (size_t)row * 768 + col) =
                __floats2half2_rn(acc[nt][0] * i0, acc[nt][1] * i0);
            *reinterpret_cast<__half2*>(A16 + (size_t)(row + 8) * 768 + col) =
                __floats2half2_rn(acc[nt][2] * i1, acc[nt][3] * i1);
        }
    }
}

// ---------------------------------------------------------------------------
extern "C" void kernel_launch(void* const* d_in, const int* in_sizes, int n_in,
                              void* d_out, int out_size)
{
    const float* x    = (const float*)d_in[0];
    const float* mask = (const float*)d_in[1];
    const float* Wq   = (const float*)d_in[2];
    const float* bq   = (const float*)d_in[3];
    const float* Wk   = (const float*)d_in[4];
    const float* bk   = (const float*)d_in[5];
    const float* Wv   = (const float*)d_in[6];
    const float* bv   = (const float*)d_in[7];
    const float* Wo   = (const float*)d_in[8];
    const float* bo   = (const float*)d_in[9];
    float* out = (float*)d_out;

    float *biasc;
    __half *qkv16, *xh, *a16, *wh, *wl, *woh, *wol;
    cudaGetSymbolAddress((void**)&qkv16, g_qkv16);
    cudaGetSymbolAddress((void**)&xh,    g_xh);
    cudaGetSymbolAddress((void**)&a16,   g_a16);
    cudaGetSymbolAddress((void**)&wh,    g_wh);
    cudaGetSymbolAddress((void**)&wl,    g_wl);
    cudaGetSymbolAddress((void**)&woh,   g_woh);
    cudaGetSymbolAddress((void**)&wol,   g_wol);
    cudaGetSymbolAddress((void**)&biasc, g_biasc);

    cudaFuncSetAttribute(gemm_f16, cudaFuncAttributeMaxDynamicSharedMemorySize, F_SMEM);

    const dim3 wgrid(24, 24), wblk(32, 8);

    // prep
    cvt_x_kernel<<<(int)(((size_t)M * 768) / 8 / 256), 256>>>(x, xh);
    wsplit16_kernel<<<wgrid, wblk>>>(Wq, wh, wl, 0);
    wsplit16_kernel<<<wgrid, wblk>>>(Wk, wh, wl, 768);
    wsplit16_kernel<<<wgrid, wblk>>>(Wv, wh, wl, 1536);
    wsplit16_kernel<<<wgrid, wblk>>>(Wo, woh, wol, 0);
    bias_concat_kernel<<<3, 768>>>(bq, bk, bv, biasc);

    // merged QKV projection -> fp16
    gemm_f16<<<dim3(18, 512), 256, F_SMEM>>>(xh, wh, wl, biasc, mask,
                                             nullptr, qkv16, 1);

    // linear-attention core (tensor cores)
    kv_tc_kernel<<<dim3(Bb * Hh, 4), 128>>>(qkv16);
    kv_reduce_kernel<<<Bb * Hh, 128>>>();
    num_tc_kernel<<<dim3(Bb * Hh, Ss / 256), 128>>>(qkv16, a16);

    // output projection -> fp32 d_out
    gemm_f16<<<dim3(6, 512), 256, F_SMEM>>>(a16, woh, wol, bo, mask,
                                            out, nullptr, 0);
}

// round 9
// speedup vs baseline: 6.3922x; 1.4075x over previous
#include <cuda_runtime.h>
#include <cuda_fp16.h>
#include <math.h>
#include <stdint.h>

// Problem constants
#define Bb   16
#define Ss   4096
#define Hh   12
#define Dd   64
constexpr int M = Bb * Ss;   // 65536
constexpr int NQKV = 2304;   // merged Q|K|V columns

// ---------------------------------------------------------------------------
// Scratch (device globals)
// ---------------------------------------------------------------------------
__device__ __half g_qkv16[(size_t)M * NQKV];      // Q | K | V fp16
__device__ __half g_xh[(size_t)M * 768];          // x fp16
__device__ __half g_a16[(size_t)M * 768];         // attention output fp16
__device__ __half g_wh[(size_t)NQKV * 768];       // Wqkv^T fp16
__device__ __half g_woh[768 * 768];               // Wo^T fp16
__device__ float  g_biasc[NQKV];
__device__ float  g_kvp[4][Bb * Hh][64 * 72];     // kv partials (fp32)
__device__ __half g_kvt[Bb * Hh][64 * 72];        // reduced kv+ksum (fp16)

// ---------------------------------------------------------------------------
// PTX helpers (sm_80-compatible: cp.async, ldmatrix, mma.sync)
// ---------------------------------------------------------------------------
__device__ __forceinline__ uint32_t smem_u32(const void* p) {
    uint32_t a;
    asm("{ .reg .u64 t; cvta.to.shared.u64 t, %1; cvt.u32.u64 %0, t; }"
        : "=r"(a) : "l"(p));
    return a;
}

__device__ __forceinline__ void cpa16(uint32_t dst, const void* src) {
    asm volatile("cp.async.cg.shared.global [%0], [%1], 16;" :: "r"(dst), "l"(src) : "memory");
}
#define CP_COMMIT() asm volatile("cp.async.commit_group;" ::: "memory")
#define CP_WAIT(n)  asm volatile("cp.async.wait_group %0;" :: "n"(n) : "memory")

__device__ __forceinline__ void ldsm4(uint32_t* r, uint32_t addr) {
    asm volatile("ldmatrix.sync.aligned.m8n8.x4.shared.b16 {%0,%1,%2,%3}, [%4];"
                 : "=r"(r[0]), "=r"(r[1]), "=r"(r[2]), "=r"(r[3]) : "r"(addr));
}
__device__ __forceinline__ void ldsm4t(uint32_t* r, uint32_t addr) {
    asm volatile("ldmatrix.sync.aligned.m8n8.x4.trans.shared.b16 {%0,%1,%2,%3}, [%4];"
                 : "=r"(r[0]), "=r"(r[1]), "=r"(r[2]), "=r"(r[3]) : "r"(addr));
}
__device__ __forceinline__ void ldsm2t(uint32_t* r, uint32_t addr) {
    asm volatile("ldmatrix.sync.aligned.m8n8.x2.trans.shared.b16 {%0,%1}, [%2];"
                 : "=r"(r[0]), "=r"(r[1]) : "r"(addr));
}

__device__ __forceinline__ void mma_f16(float* c, const uint32_t* a, const uint32_t* b) {
    asm volatile(
        "mma.sync.aligned.m16n8k16.row.col.f32.f16.f16.f32 "
        "{%0,%1,%2,%3}, {%4,%5,%6,%7}, {%8,%9}, {%0,%1,%2,%3};"
        : "+f"(c[0]), "+f"(c[1]), "+f"(c[2]), "+f"(c[3])
        : "r"(a[0]), "r"(a[1]), "r"(a[2]), "r"(a[3]), "r"(b[0]), "r"(b[1]));
}

__device__ __forceinline__ float epi_f(float v, float mk, int epi) {
    if (epi >= 1) v *= mk;
    if (epi == 2) { v = (v > 0.0f) ? (v + 1.0f) : expf(v); v *= 0.125f; }
    return v;
}

// ---------------------------------------------------------------------------
// fp16 single-term GEMM:  C = A(fp16) @ B^T   (B pre-transposed [N][K])
// CTA tile 128x128x32, warp tile 64x32, 3-stage cp.async, 2 CTAs/SM.
// Smem/stage: A 8K | B 8K = 16KB. XOR swizzle on 16B chunks.
// mode 1 (QKV): writes fp16 to C16 (ld 2304); epi elu for bx<12, mask else
// mode 0 (out): writes fp32 to C32 (ld 768); plain bias
// ---------------------------------------------------------------------------
constexpr int F_STAGE = 16384;
constexpr int F_SMEM  = 3 * F_STAGE;
constexpr int FA = 0, FB = 8192;

__device__ __forceinline__ void stage_load_f16(
    uint32_t sbase,
    const __half* __restrict__ A, const __half* __restrict__ B,
    int mb, int nb, int k0, int tid)
{
    #pragma unroll
    for (int t = 0; t < 2; t++) {
        const int lin = tid + t * 256;   // 512 slots: 128 rows x 4 chunks
        const int r = lin >> 2;
        const int c = lin & 3;
        const uint32_t so = (uint32_t)r * 64 + ((uint32_t)(c ^ ((r >> 1) & 3)) << 4);
        cpa16(sbase + FA + so, A + (size_t)(mb + r) * 768 + k0 + c * 8);
        cpa16(sbase + FB + so, B + (size_t)(nb + r) * 768 + k0 + c * 8);
    }
}

__global__ void __launch_bounds__(256, 2)
gemm_f16(const __half* __restrict__ A, const __half* __restrict__ B,
         const float* __restrict__ bias, const float* __restrict__ mask,
         float* __restrict__ C32, __half* __restrict__ C16, int mode)
{
    extern __shared__ char smraw[];
    const uint32_t sm0 = smem_u32(smraw);

    const int tid  = threadIdx.x;
    const int lane = tid & 31;
    const int warp = tid >> 5;
    const int wm = warp & 1;        // 2 warps in M -> 64 rows
    const int wn = warp >> 1;       // 4 warps in N -> 32 cols
    const int nb = blockIdx.x * 128;
    const int mb = blockIdx.y * 128;
    const int epi = (mode == 0) ? 0 : ((blockIdx.x < 12) ? 2 : 1);

    uint32_t baseA[4], maskA[4];
    const int arow0 = wm * 64 + (lane & 15);
    const uint32_t acs = (uint32_t)(lane >> 4);
    #pragma unroll
    for (int mt = 0; mt < 4; mt++) {
        const int r = arow0 + mt * 16;
        baseA[mt] = (uint32_t)r * 64;
        maskA[mt] = (uint32_t)((r >> 1) & 3);
    }
    uint32_t baseB[2], maskB[2];
    const int brow0 = wn * 32 + (lane & 7) + ((lane >> 4) << 3);
    const uint32_t bcs = (uint32_t)((lane >> 3) & 1);
    #pragma unroll
    for (int bt = 0; bt < 2; bt++) {
        const int r = brow0 + bt * 16;
        baseB[bt] = (uint32_t)r * 64;
        maskB[bt] = (uint32_t)((r >> 1) & 3);
    }

    float acc[4][4][4] = {};

    stage_load_f16(sm0 + 0 * F_STAGE, A, B, mb, nb, 0, tid);
    CP_COMMIT();
    stage_load_f16(sm0 + 1 * F_STAGE, A, B, mb, nb, 32, tid);
    CP_COMMIT();

    #pragma unroll 1
    for (int s = 0; s < 24; s++) {
        if (s < 23) { CP_WAIT(1); } else { CP_WAIT(0); }
        __syncthreads();

        const uint32_t sb = sm0 + (s % 3) * F_STAGE;
        #pragma unroll
        for (int ks = 0; ks < 2; ks++) {
            const uint32_t kc = (uint32_t)(ks * 2);

            uint32_t bf[4][2];
            #pragma unroll
            for (int bt = 0; bt < 2; bt++) {
                const uint32_t off = baseB[bt] + (((kc + bcs) ^ maskB[bt]) << 4);
                uint32_t tmp[4];
                ldsm4(tmp, sb + FB + off);
                bf[2 * bt][0] = tmp[0]; bf[2 * bt][1] = tmp[1];
                bf[2 * bt + 1][0] = tmp[2]; bf[2 * bt + 1][1] = tmp[3];
            }
            uint32_t a[4][4];
            #pragma unroll
            for (int mt = 0; mt < 4; mt++)
                ldsm4(a[mt], sb + FA + baseA[mt] + (((kc + acs) ^ maskA[mt]) << 4));

            #pragma unroll
            for (int mt = 0; mt < 4; mt++)
                #pragma unroll
                for (int nt = 0; nt < 4; nt++)
                    mma_f16(acc[mt][nt], a[mt], bf[nt]);
        }

        if (s + 2 < 24) {
            stage_load_f16(sm0 + ((s + 2) % 3) * F_STAGE, A, B,
                           mb, nb, (s + 2) * 32, tid);
            CP_COMMIT();
        }
    }

    // epilogue
    const int r0 = lane >> 2;
    const int c0 = (lane & 3) * 2;
    #pragma unroll
    for (int mt = 0; mt < 4; mt++) {
        const int mrow = mb + wm * 64 + mt * 16 + r0;
        const float mk0 = (epi >= 1) ? mask[mrow] : 1.0f;
        const float mk1 = (epi >= 1) ? mask[mrow + 8] : 1.0f;
        #pragma unroll
        for (int nt = 0; nt < 4; nt++) {
            const int col = nb + wn * 32 + nt * 8 + c0;
            const float b0 = bias[col], b1 = bias[col + 1];
            const float v00 = epi_f(acc[mt][nt][0] + b0, mk0, epi);
            const float v01 = epi_f(acc[mt][nt][1] + b1, mk0, epi);
            const float v10 = epi_f(acc[mt][nt][2] + b0, mk1, epi);
            const float v11 = epi_f(acc[mt][nt][3] + b1, mk1, epi);
            if (mode == 1) {
                *reinterpret_cast<__half2*>(C16 + (size_t)mrow * NQKV + col) =
                    __floats2half2_rn(v00, v01);
                *reinterpret_cast<__half2*>(C16 + (size_t)(mrow + 8) * NQKV + col) =
                    __floats2half2_rn(v10, v11);
            } else {
                *reinterpret_cast<float2*>(C32 + (size_t)mrow * 768 + col) =
                    make_float2(v00, v01);
                *reinterpret_cast<float2*>(C32 + (size_t)(mrow + 8) * 768 + col) =
                    make_float2(v10, v11);
            }
        }
    }
}

// ---------------------------------------------------------------------------
// Prep kernels
// ---------------------------------------------------------------------------
__global__ void __launch_bounds__(256)
cvt_x_kernel(const float* __restrict__ x, __half* __restrict__ xh)
{
    const size_t i = ((size_t)blockIdx.x * 256 + threadIdx.x) * 8;
    const float4 v0 = *reinterpret_cast<const float4*>(x + i);
    const float4 v1 = *reinterpret_cast<const float4*>(x + i + 4);
    __half2 h[4];
    h[0] = __floats2half2_rn(v0.x, v0.y);
    h[1] = __floats2half2_rn(v0.z, v0.w);
    h[2] = __floats2half2_rn(v1.x, v1.y);
    h[3] = __floats2half2_rn(v1.z, v1.w);
    *reinterpret_cast<uint4*>(xh + i) = *reinterpret_cast<uint4*>(h);
}

// transpose + fp16 convert:  out[noff+n][k] = fp16(W[k][n])
__global__ void __launch_bounds__(256)
wt16_kernel(const float* __restrict__ W, __half* __restrict__ hi, int noff)
{
    __shared__ float t[32][33];
    const int bx = blockIdx.x * 32, by = blockIdx.y * 32;
    const int tx = threadIdx.x, ty = threadIdx.y;
    #pragma unroll
    for (int i = 0; i < 32; i += 8)
        t[ty + i][tx] = W[(size_t)(by + ty + i) * 768 + bx + tx];
    __syncthreads();
    #pragma unroll
    for (int i = 0; i < 32; i += 8)
        hi[(size_t)(noff + bx + ty + i) * 768 + by + tx] = __float2half(t[tx][ty + i]);
}

__global__ void bias_concat_kernel(const float* bq, const float* bk, const float* bv,
                                   float* out)
{
    const int i = threadIdx.x;
    const float* src = (blockIdx.x == 0) ? bq : (blockIdx.x == 1) ? bk : bv;
    out[blockIdx.x * 768 + i] = src[i];
}

// ---------------------------------------------------------------------------
// kv = K^T V (+ ksum in col 64) via fp16 tensor cores.
// grid (192, 4): one (b,h) x 1024-seq chunk per block, 128 threads.
// ---------------------------------------------------------------------------
__global__ void __launch_bounds__(128)
kv_tc_kernel(const __half* __restrict__ QKV16)
{
    __shared__ __half kb[2][64][72];
    __shared__ __half vb[2][64][72];

    const int bh = blockIdx.x, ch = blockIdx.y;
    const int b = bh / Hh, h = bh % Hh;
    const int tid = threadIdx.x, lane = tid & 31, warp = tid >> 5;

    {
        const int bf = tid >> 6, r = tid & 63;
        vb[bf][r][64] = __float2half(1.0f);
        #pragma unroll
        for (int c = 65; c < 72; c++) vb[bf][r][c] = __float2half(0.0f);
    }
    __syncthreads();

    const int chunk0 = ch * 1024;
    const int d0 = warp * 16;

    #define KV_LOAD(st, s0)                                                       \
        do {                                                                      \
            _Pragma("unroll")                                                     \
            for (int t = 0; t < 4; t++) {                                         \
                const int lin = tid + t * 128;                                    \
                const int r = lin >> 3, c = lin & 7;                              \
                const size_t base =                                               \
                    ((size_t)(b * Ss + (s0) + r)) * NQKV + h * 64 + c * 8;        \
                cpa16(smem_u32(&kb[st][r][c * 8]), QKV16 + base + 768);           \
                cpa16(smem_u32(&vb[st][r][c * 8]), QKV16 + base + 1536);          \
            }                                                                     \
            CP_COMMIT();                                                          \
        } while (0)

    float acc[9][4] = {};

    KV_LOAD(0, chunk0);
    KV_LOAD(1, chunk0 + 64);

    const int g = lane >> 3, l = lane & 7;

    #pragma unroll 1
    for (int it = 0; it < 16; it++) {
        if (it < 15) { CP_WAIT(1); } else { CP_WAIT(0); }
        __syncthreads();

        const int st = it & 1;
        #pragma unroll
        for (int ks = 0; ks < 4; ks++) {
            const int srow = ks * 16 + ((g & 2) ? 8 : 0) + l;
            const int scol = d0 + ((g & 1) ? 8 : 0);
            uint32_t a[4];
            ldsm4t(a, smem_u32(&kb[st][srow][scol]));

            uint32_t bfrag[9][2];
            const int vrow = ks * 16 + ((g & 1) ? 8 : 0) + l;
            #pragma unroll
            for (int np = 0; np < 4; np++) {
                const int vcol = np * 16 + ((g & 2) ? 8 : 0);
                uint32_t t4[4];
                ldsm4t(t4, smem_u32(&vb[st][vrow][vcol]));
                bfrag[2 * np][0] = t4[0];     bfrag[2 * np][1] = t4[1];
                bfrag[2 * np + 1][0] = t4[2]; bfrag[2 * np + 1][1] = t4[3];
            }
            {
                const int vr2 = ks * 16 + ((lane >> 3) & 1) * 8 + l;
                uint32_t t2[2];
                ldsm2t(t2, smem_u32(&vb[st][vr2][64]));
                bfrag[8][0] = t2[0]; bfrag[8][1] = t2[1];
            }
            #pragma unroll
            for (int nt = 0; nt < 9; nt++) mma_f16(acc[nt], a, bfrag[nt]);
        }
        __syncthreads();
        if (it + 2 < 16) KV_LOAD(st, chunk0 + (it + 2) * 64);
    }
    #undef KV_LOAD

    float* dst = &g_kvp[ch][bh][0];
    const int r = lane >> 2, cp = (lane & 3) * 2;
    #pragma unroll
    for (int nt = 0; nt < 9; nt++) {
        const int col = nt * 8 + cp;
        *reinterpret_cast<float2*>(dst + (d0 + r) * 72 + col) =
            make_float2(acc[nt][0], acc[nt][1]);
        *reinterpret_cast<float2*>(dst + (d0 + r + 8) * 72 + col) =
            make_float2(acc[nt][2], acc[nt][3]);
    }
}

__global__ void __launch_bounds__(128)
kv_reduce_kernel()
{
    const int bh = blockIdx.x;
    for (int i = threadIdx.x; i < 64 * 72; i += 128) {
        const float s = g_kvp[0][bh][i] + g_kvp[1][bh][i]
                      + g_kvp[2][bh][i] + g_kvp[3][bh][i];
        g_kvt[bh][i] = __float2half(s);
    }
}

// ---------------------------------------------------------------------------
// num|den = Q @ kv[64x72] (col 64 = den); out = num/den -> fp16 a16.
// ---------------------------------------------------------------------------
__global__ void __launch_bounds__(128)
num_tc_kernel(const __half* __restrict__ QKV16, __half* __restrict__ A16)
{
    __shared__ __half kvs[64][72];

    const int bh = blockIdx.x;
    const int b = bh / Hh, h = bh % Hh;
    const int tid = threadIdx.x, lane = tid & 31, warp = tid >> 5;
    const int s0 = blockIdx.y * 256;

    {
        const uint32_t* src = reinterpret_cast<const uint32_t*>(&g_kvt[bh][0]);
        uint32_t* dst = reinterpret_cast<uint32_t*>(&kvs[0][0]);
        for (int i = tid; i < 64 * 72 / 2; i += 128) dst[i] = src[i];
    }
    __syncthreads();

    uint32_t bfr[4][9][2];
    const int g = lane >> 3, l = lane & 7;
    #pragma unroll
    for (int ks = 0; ks < 4; ks++) {
        const int vrow = ks * 16 + ((g & 1) ? 8 : 0) + l;
        #pragma unroll
        for (int np = 0; np < 4; np++) {
            const int vcol = np * 16 + ((g & 2) ? 8 : 0);
            uint32_t t4[4];
            ldsm4t(t4, smem_u32(&kvs[vrow][vcol]));
            bfr[ks][2 * np][0] = t4[0];     bfr[ks][2 * np][1] = t4[1];
            bfr[ks][2 * np + 1][0] = t4[2]; bfr[ks][2 * np + 1][1] = t4[3];
        }
        const int vr2 = ks * 16 + ((lane >> 3) & 1) * 8 + l;
        uint32_t t2[2];
        ldsm2t(t2, smem_u32(&kvs[vr2][64]));
        bfr[ks][8][0] = t2[0]; bfr[ks][8][1] = t2[1];
    }

    const uint32_t* Q32 = reinterpret_cast<const uint32_t*>(QKV16);
    const int rbase = b * Ss + s0 + warp * 64;

    #pragma unroll 1
    for (int mt = 0; mt < 4; mt++) {
        float acc[9][4] = {};
        const int row = rbase + mt * 16 + (lane >> 2);
        #pragma unroll
        for (int ks = 0; ks < 4; ks++) {
            const int cb = h * 64 + ks * 16 + (lane & 3) * 2;
            uint32_t a[4];
            a[0] = Q32[((size_t)row * NQKV + cb) >> 1];
            a[1] = Q32[((size_t)(row + 8) * NQKV + cb) >> 1];
            a[2] = Q32[((size_t)row * NQKV + cb + 8) >> 1];
            a[3] = Q32[((size_t)(row + 8) * NQKV + cb + 8) >> 1];
            #pragma unroll
            for (int nt = 0; nt < 9; nt++) mma_f16(acc[nt], a, bfr[ks][nt]);
        }

        const float den0 = __shfl_sync(0xFFFFFFFFu, acc[8][0], lane & 28);
        const float den1 = __shfl_sync(0xFFFFFFFFu, acc[8][2], lane & 28);
        const float i0 = 1.0f / den0, i1 = 1.0f / den1;
        #pragma unroll
        for (int nt = 0; nt < 8; nt++) {
            const int col = h * 64 + nt * 8 + (lane & 3) * 2;
            *reinterpret_cast<__half2*>(A16 + (size_t)row * 768 + col) =
                __floats2half2_rn(acc[nt][0] * i0, acc[nt][1] * i0);
            *reinterpret_cast<__half2*>(A16 + (size_t)(row + 8) * 768 + col) =
                __floats2half2_rn(acc[nt][2] * i1, acc[nt][3] * i1);
        }
    }
}

// ---------------------------------------------------------------------------
extern "C" void kernel_launch(void* const* d_in, const int* in_sizes, int n_in,
                              void* d_out, int out_size)
{
    const float* x    = (const float*)d_in[0];
    const float* mask = (const float*)d_in[1];
    const float* Wq   = (const float*)d_in[2];
    const float* bq   = (const float*)d_in[3];
    const float* Wk   = (const float*)d_in[4];
    const float* bk   = (const float*)d_in[5];
    const float* Wv   = (const float*)d_in[6];
    const float* bv   = (const float*)d_in[7];
    const float* Wo   = (const float*)d_in[8];
    const float* bo   = (const float*)d_in[9];
    float* out = (float*)d_out;

    float *biasc;
    __half *qkv16, *xh, *a16, *wh, *woh;
    cudaGetSymbolAddress((void**)&qkv16, g_qkv16);
    cudaGetSymbolAddress((void**)&xh,    g_xh);
    cudaGetSymbolAddress((void**)&a16,   g_a16);
    cudaGetSymbolAddress((void**)&wh,    g_wh);
    cudaGetSymbolAddress((void**)&woh,   g_woh);
    cudaGetSymbolAddress((void**)&biasc, g_biasc);

    cudaFuncSetAttribute(gemm_f16, cudaFuncAttributeMaxDynamicSharedMemorySize, F_SMEM);

    const dim3 wgrid(24, 24), wblk(32, 8);

    // prep
    cvt_x_kernel<<<(int)(((size_t)M * 768) / 8 / 256), 256>>>(x, xh);
    wt16_kernel<<<wgrid, wblk>>>(Wq, wh, 0);
    wt16_kernel<<<wgrid, wblk>>>(Wk, wh, 768);
    wt16_kernel<<<wgrid, wblk>>>(Wv, wh, 1536);
    wt16_kernel<<<wgrid, wblk>>>(Wo, woh, 0);
    bias_concat_kernel<<<3, 768>>>(bq, bk, bv, biasc);

    // merged QKV projection -> fp16 (single-term)
    gemm_f16<<<dim3(18, 512), 256, F_SMEM>>>(xh, wh, biasc, mask,
                                             nullptr, qkv16, 1);

    // linear-attention core (tensor cores)
    kv_tc_kernel<<<dim3(Bb * Hh, 4), 128>>>(qkv16);
    kv_reduce_kernel<<<Bb * Hh, 128>>>();
    num_tc_kernel<<<dim3(Bb * Hh, Ss / 256), 128>>>(qkv16, a16);

    // output projection -> fp32 d_out (single-term)
    gemm_f16<<<dim3(6, 512), 256, F_SMEM>>>(a16, woh, bo, mask,
                                            out, nullptr, 0);
}